// round 11
// baseline (speedup 1.0000x reference)
#include <cuda_runtime.h>
#include <math.h>
#include <float.h>
#include <stdint.h>

#define B 8
#define SEQ 12
#define NN 1000
#define E 16000
#define HID 128
#define HEADS 8
#define DH 16
#define M_ROWS (B*NN)          /* 8000 */

#define AT_STRIDE 68           /* old FFMA gemm: 64 rows + 4 pad */
#define GEMM_SMEM (HID*HID*4 + HID*AT_STRIDE*4)   /* 64KB W + 34KB A^T */

#define SA_STRIDE 132          /* mma gemm A tile stride (floats) */
#define SW_STRIDE 132          /* mma gemm W^T tile stride */
#define MMA_SMEM ((64*SA_STRIDE + 2*HID*SW_STRIDE)*4)   /* 33792+135168=168960B */

// ---------------- static device scratch ----------------
__device__ float    g_hin[(size_t)SEQ*B*NN*HID];
__device__ float    g_y  [(size_t)M_ROWS*HID];
__device__ float    g_hp [(size_t)M_ROWS*HID];
__device__ float    g_k1 [(size_t)M_ROWS*HID];
__device__ float    g_k2 [(size_t)M_ROWS*HID];
__device__ float    g_k3 [(size_t)M_ROWS*HID];
__device__ float    g_tmp[(size_t)M_ROWS*HID];
__device__ float    g_el [(size_t)M_ROWS*HEADS];
__device__ float    g_er [(size_t)M_ROWS*HEADS];
__device__ unsigned g_whi[HID*HID];
__device__ unsigned g_wlo[HID*HID];
__device__ int      g_cnt[NN];
__device__ int      g_cur[NN];
__device__ int      g_off[NN+1];
__device__ int      g_eidx[E];

// ---------------- tf32 helpers ----------------
__device__ __forceinline__ unsigned f2tf(float x){
    unsigned r; asm("cvt.rna.tf32.f32 %0, %1;" : "=r"(r) : "f"(x)); return r;
}

#define MMA_TF32(c, a0,a1,a2,a3, b0,b1) \
    asm volatile("mma.sync.aligned.m16n8k8.row.col.f32.tf32.tf32.f32 " \
        "{%0,%1,%2,%3}, {%4,%5,%6,%7}, {%8,%9}, {%0,%1,%2,%3};" \
        : "+f"((c)[0]), "+f"((c)[1]), "+f"((c)[2]), "+f"((c)[3]) \
        : "r"(a0), "r"(a1), "r"(a2), "r"(a3), "r"(b0), "r"(b1))

// ---------------- fused init: inproj + y=h[:,0] + CSR zero ----------------
__global__ void k_init(const float* __restrict__ inp, const float* __restrict__ w_in,
                       const float* __restrict__ b_in, float* __restrict__ hin,
                       float* __restrict__ y, int* cnt, int* cur){
    int row = blockIdx.x;
    int t = threadIdx.x;
    if (blockIdx.x < 8){
        int q = blockIdx.x*128 + t;
        if (q < NN){ cnt[q] = 0; cur[q] = 0; }
    }
    int b = row / (SEQ*NN);
    int s = (row / NN) % SEQ;
    int n = row % NN;
    float x0 = inp[(size_t)row*2 + 0];
    float x1 = inp[(size_t)row*2 + 1];
    float v = fmaf(x0, w_in[t], fmaf(x1, w_in[HID+t], b_in[t]));
    hin[(((size_t)s*B + b)*NN + n)*HID + t] = v;
    if (s == 0) y[((size_t)b*NN + n)*HID + t] = v;
}

// ---------------- w_gat tf32 hi/lo split (once per launch) ----------------
__global__ void k_wsplit(const float* __restrict__ w, unsigned* whi, unsigned* wlo){
    int i = blockIdx.x*256 + threadIdx.x;
    if (i < HID*HID){
        float x = w[i];
        unsigned h = f2tf(x);
        whi[i] = h;
        wlo[i] = f2tf(x - __uint_as_float(h));
    }
}

// ---------------- CSR construction (deterministic) ----------------
__global__ void k_csr_count(const int* __restrict__ dst, int* cnt){
    int e = blockIdx.x*blockDim.x + threadIdx.x;
    if (e < E) atomicAdd(&cnt[dst[e]], 1);
}
__global__ void k_csr_scan(const int* __restrict__ cnt, int* off){
    __shared__ int s[1024];
    int t = threadIdx.x;
    s[t] = (t < NN) ? cnt[t] : 0;
    __syncthreads();
    #pragma unroll
    for (int o = 1; o < 1024; o <<= 1){
        int v = (t >= o) ? s[t-o] : 0;
        __syncthreads();
        s[t] += v;
        __syncthreads();
    }
    if (t == 0) off[0] = 0;
    if (t < NN) off[t+1] = s[t];
}
__global__ void k_csr_fill(const int* __restrict__ dst, const int* __restrict__ off,
                           int* cur, int* eidx){
    int e = blockIdx.x*blockDim.x + threadIdx.x;
    if (e < E){
        int d = dst[e];
        int p = atomicAdd(&cur[d], 1);
        eidx[off[d] + p] = e;
    }
}
__global__ void k_csr_sort(const int* __restrict__ off, int* eidx){
    if (threadIdx.x != 0) return;
    int n = blockIdx.x;
    int a = off[n], b = off[n+1];
    for (int i = a+1; i < b; i++){
        int v = eidx[i]; int j = i-1;
        while (j >= a && eidx[j] > v){ eidx[j+1] = eidx[j]; j--; }
        eidx[j+1] = v;
    }
}

// ============ tensor-core GEMM (GAT path): hp = (A0 + c1*A1) @ W_gat ==========
// 3xTF32: W pre-split (hi/lo in global, staged transposed to smem); A split at
// runtime. 64x128 tile/block, grid 125, 512 threads = 16 warps, each 16x32 tile
// via mma.m16n8k8. el/er epilogue included.
__global__ void __launch_bounds__(512) k_gemm_mma(
    const float* __restrict__ A0, const float* __restrict__ A1, float c1,
    const unsigned* __restrict__ WHi, const unsigned* __restrict__ WLo,
    float* __restrict__ C,
    float* __restrict__ el, float* __restrict__ er,
    const float* __restrict__ a_l, const float* __restrict__ a_r)
{
    extern __shared__ float smem[];
    float*    sA  = smem;                                   // [64][SA_STRIDE]
    unsigned* sWh = (unsigned*)(smem + 64*SA_STRIDE);       // [128 n][SW_STRIDE] (k contig)
    unsigned* sWl = sWh + HID*SW_STRIDE;

    int tid  = threadIdx.x;
    int lane = tid & 31, w = tid >> 5;
    int row0 = blockIdx.x * 64;
    int mrow = (w & 3) * 16;
    int ncol = (w >> 2) * 32;
    int g = lane >> 2;        // 0..7
    int t = lane & 3;         // 0..3

    // ---- stage W hi/lo transposed: sW[n*SW_STRIDE + k] ----
    {
        const uint4* Wh4 = (const uint4*)WHi;
        const uint4* Wl4 = (const uint4*)WLo;
        #pragma unroll
        for (int i = tid; i < HID*32; i += 512){
            int n4 = i >> 7, k = i & 127;        // warp: k consecutive, n4 fixed
            uint4 vh = Wh4[(size_t)k*32 + n4];
            uint4 vl = Wl4[(size_t)k*32 + n4];
            int n0 = n4*4;
            sWh[(n0+0)*SW_STRIDE + k] = vh.x;
            sWh[(n0+1)*SW_STRIDE + k] = vh.y;
            sWh[(n0+2)*SW_STRIDE + k] = vh.z;
            sWh[(n0+3)*SW_STRIDE + k] = vh.w;
            sWl[(n0+0)*SW_STRIDE + k] = vl.x;
            sWl[(n0+1)*SW_STRIDE + k] = vl.y;
            sWl[(n0+2)*SW_STRIDE + k] = vl.z;
            sWl[(n0+3)*SW_STRIDE + k] = vl.w;
        }
    }
    // ---- stage A row-major with fused axpy ----
    {
        const float4* A04 = (const float4*)A0;
        const float4* A14 = (const float4*)A1;
        #pragma unroll
        for (int i = tid; i < 64*32; i += 512){
            int r = i >> 5, c4 = i & 31;
            float4 v = A04[(size_t)(row0+r)*32 + c4];
            if (A1){
                float4 u = A14[(size_t)(row0+r)*32 + c4];
                v.x = fmaf(c1,u.x,v.x); v.y = fmaf(c1,u.y,v.y);
                v.z = fmaf(c1,u.z,v.z); v.w = fmaf(c1,u.w,v.w);
            }
            *reinterpret_cast<float4*>(&sA[r*SA_STRIDE + c4*4]) = v;
        }
    }
    __syncthreads();

    float acc[4][4];
    #pragma unroll
    for (int i=0;i<4;i++)
        #pragma unroll
        for (int j=0;j<4;j++) acc[i][j] = 0.f;

    const float* sArow1 = sA + (mrow + g)*SA_STRIDE;
    const float* sArow2 = sArow1 + 8*SA_STRIDE;

    #pragma unroll 4
    for (int ks = 0; ks < 16; ks++){
        int k0 = ks*8;
        // A fragment (fp32 -> tf32 hi/lo)
        float a0f = sArow1[k0 + t];
        float a1f = sArow2[k0 + t];
        float a2f = sArow1[k0 + t + 4];
        float a3f = sArow2[k0 + t + 4];
        unsigned ah0 = f2tf(a0f), ah1 = f2tf(a1f), ah2 = f2tf(a2f), ah3 = f2tf(a3f);
        unsigned al0 = f2tf(a0f - __uint_as_float(ah0));
        unsigned al1 = f2tf(a1f - __uint_as_float(ah1));
        unsigned al2 = f2tf(a2f - __uint_as_float(ah2));
        unsigned al3 = f2tf(a3f - __uint_as_float(ah3));
        #pragma unroll
        for (int nt = 0; nt < 4; nt++){
            int bi = (ncol + nt*8 + g)*SW_STRIDE + k0 + t;
            unsigned bh0 = sWh[bi], bh1 = sWh[bi+4];
            unsigned bl0 = sWl[bi], bl1 = sWl[bi+4];
            MMA_TF32(acc[nt], ah0,ah1,ah2,ah3, bh0,bh1);
            MMA_TF32(acc[nt], ah0,ah1,ah2,ah3, bl0,bl1);
            MMA_TF32(acc[nt], al0,al1,al2,al3, bh0,bh1);
        }
    }

    // ---- store hp ----
    {
        size_t r1 = row0 + mrow + g;
        #pragma unroll
        for (int nt=0; nt<4; nt++){
            int col = ncol + nt*8 + t*2;
            *reinterpret_cast<float2*>(C + r1*HID + col)     = make_float2(acc[nt][0], acc[nt][1]);
            *reinterpret_cast<float2*>(C + (r1+8)*HID + col) = make_float2(acc[nt][2], acc[nt][3]);
        }
    }
    // ---- el/er epilogue: warp owns heads h0, h0+1; rows mrow+g, +8 ----
    {
        int h0 = ncol >> 4;
        float pl[2][2] = {{0.f,0.f},{0.f,0.f}};
        float pr[2][2] = {{0.f,0.f},{0.f,0.f}};
        #pragma unroll
        for (int nt=0; nt<4; nt++){
            int hp_ = nt >> 1;
            int d   = (nt & 1)*8 + t*2;
            int h   = h0 + hp_;
            float l0 = a_l[h*DH + d],  l1 = a_l[h*DH + d + 1];
            float r0 = a_r[h*DH + d],  r1 = a_r[h*DH + d + 1];
            pl[hp_][0] += acc[nt][0]*l0 + acc[nt][1]*l1;
            pl[hp_][1] += acc[nt][2]*l0 + acc[nt][3]*l1;
            pr[hp_][0] += acc[nt][0]*r0 + acc[nt][1]*r1;
            pr[hp_][1] += acc[nt][2]*r0 + acc[nt][3]*r1;
        }
        #pragma unroll
        for (int hp_=0; hp_<2; hp_++){
            #pragma unroll
            for (int rh=0; rh<2; rh++){
                pl[hp_][rh] += __shfl_xor_sync(0xffffffffu, pl[hp_][rh], 1);
                pl[hp_][rh] += __shfl_xor_sync(0xffffffffu, pl[hp_][rh], 2);
                pr[hp_][rh] += __shfl_xor_sync(0xffffffffu, pr[hp_][rh], 1);
                pr[hp_][rh] += __shfl_xor_sync(0xffffffffu, pr[hp_][rh], 2);
            }
        }
        if (t == 0){
            int r1 = row0 + mrow + g;
            el[(size_t)r1*HEADS + h0]       = pl[0][0];
            el[(size_t)(r1+8)*HEADS + h0]   = pl[0][1];
            el[(size_t)r1*HEADS + h0+1]     = pl[1][0];
            el[(size_t)(r1+8)*HEADS + h0+1] = pl[1][1];
            er[(size_t)r1*HEADS + h0]       = pr[0][0];
            er[(size_t)(r1+8)*HEADS + h0]   = pr[0][1];
            er[(size_t)r1*HEADS + h0+1]     = pr[1][0];
            er[(size_t)(r1+8)*HEADS + h0+1] = pr[1][1];
        }
    }
}

// ---------------- FFMA GEMM (tanh/LN + head path; proven round-10 code) ------
__global__ void __launch_bounds__(512) k_gemm(
    const float* __restrict__ A0, const float* __restrict__ A1, float c1,
    const float* __restrict__ W0,
    const float* __restrict__ A2, const float* __restrict__ W1,
    const float* __restrict__ b0, const float* __restrict__ b1,
    float* __restrict__ C, int act, int doLN)
{
    extern __shared__ float smem[];
    float* sW  = smem;
    float* sAT = smem + HID*HID;

    int row0 = blockIdx.x * 64;
    int tid = threadIdx.x;
    int tx = tid & 31, ty = tid >> 5;
    int col0 = tx * 4;

    float acc[4][4];
    #pragma unroll
    for (int i=0;i<4;i++)
        #pragma unroll
        for (int j=0;j<4;j++) acc[i][j] = 0.f;

    {
        const float4* W4 = (const float4*)W0;
        float4* sW4 = (float4*)sW;
        #pragma unroll
        for (int i = tid; i < HID*32; i += 512) sW4[i] = W4[i];
    }
    {
        const float4* A04 = (const float4*)A0;
        const float4* A14 = (const float4*)A1;
        #pragma unroll
        for (int i = tid; i < 64*32; i += 512){
            int r = i >> 5, c4 = i & 31;
            float4 v = A04[(size_t)(row0+r)*32 + c4];
            if (A1){
                float4 u = A14[(size_t)(row0+r)*32 + c4];
                v.x = fmaf(c1,u.x,v.x); v.y = fmaf(c1,u.y,v.y);
                v.z = fmaf(c1,u.z,v.z); v.w = fmaf(c1,u.w,v.w);
            }
            int k0 = c4*4;
            sAT[(k0+0)*AT_STRIDE + r] = v.x;
            sAT[(k0+1)*AT_STRIDE + r] = v.y;
            sAT[(k0+2)*AT_STRIDE + r] = v.z;
            sAT[(k0+3)*AT_STRIDE + r] = v.w;
        }
    }
    __syncthreads();
    {
        const float4* sW4 = (const float4*)sW;
        float4 w = sW4[tx];
        float4 a = *reinterpret_cast<const float4*>(sAT + ty*4);
        #pragma unroll 4
        for (int k = 0; k < HID; k++){
            int kn = (k+1) & 127;
            float4 wn = sW4[kn*32 + tx];
            float4 an = *reinterpret_cast<const float4*>(sAT + kn*AT_STRIDE + ty*4);
            acc[0][0]=fmaf(a.x,w.x,acc[0][0]); acc[0][1]=fmaf(a.x,w.y,acc[0][1]);
            acc[0][2]=fmaf(a.x,w.z,acc[0][2]); acc[0][3]=fmaf(a.x,w.w,acc[0][3]);
            acc[1][0]=fmaf(a.y,w.x,acc[1][0]); acc[1][1]=fmaf(a.y,w.y,acc[1][1]);
            acc[1][2]=fmaf(a.y,w.z,acc[1][2]); acc[1][3]=fmaf(a.y,w.w,acc[1][3]);
            acc[2][0]=fmaf(a.z,w.x,acc[2][0]); acc[2][1]=fmaf(a.z,w.y,acc[2][1]);
            acc[2][2]=fmaf(a.z,w.z,acc[2][2]); acc[2][3]=fmaf(a.z,w.w,acc[2][3]);
            acc[3][0]=fmaf(a.w,w.x,acc[3][0]); acc[3][1]=fmaf(a.w,w.y,acc[3][1]);
            acc[3][2]=fmaf(a.w,w.z,acc[3][2]); acc[3][3]=fmaf(a.w,w.w,acc[3][3]);
            w = wn; a = an;
        }
    }
    if (A2){
        __syncthreads();
        {
            const float4* W4 = (const float4*)W1;
            float4* sW4 = (float4*)sW;
            #pragma unroll
            for (int i = tid; i < HID*32; i += 512) sW4[i] = W4[i];
            const float4* A24 = (const float4*)A2;
            #pragma unroll
            for (int i = tid; i < 64*32; i += 512){
                int r = i >> 5, c4 = i & 31;
                float4 v = A24[(size_t)(row0+r)*32 + c4];
                int k0 = c4*4;
                sAT[(k0+0)*AT_STRIDE + r] = v.x;
                sAT[(k0+1)*AT_STRIDE + r] = v.y;
                sAT[(k0+2)*AT_STRIDE + r] = v.z;
                sAT[(k0+3)*AT_STRIDE + r] = v.w;
            }
        }
        __syncthreads();
        const float4* sW4 = (const float4*)sW;
        float4 w = sW4[tx];
        float4 a = *reinterpret_cast<const float4*>(sAT + ty*4);
        #pragma unroll 4
        for (int k = 0; k < HID; k++){
            int kn = (k+1) & 127;
            float4 wn = sW4[kn*32 + tx];
            float4 an = *reinterpret_cast<const float4*>(sAT + kn*AT_STRIDE + ty*4);
            acc[0][0]=fmaf(a.x,w.x,acc[0][0]); acc[0][1]=fmaf(a.x,w.y,acc[0][1]);
            acc[0][2]=fmaf(a.x,w.z,acc[0][2]); acc[0][3]=fmaf(a.x,w.w,acc[0][3]);
            acc[1][0]=fmaf(a.y,w.x,acc[1][0]); acc[1][1]=fmaf(a.y,w.y,acc[1][1]);
            acc[1][2]=fmaf(a.y,w.z,acc[1][2]); acc[1][3]=fmaf(a.y,w.w,acc[1][3]);
            acc[2][0]=fmaf(a.z,w.x,acc[2][0]); acc[2][1]=fmaf(a.z,w.y,acc[2][1]);
            acc[2][2]=fmaf(a.z,w.z,acc[2][2]); acc[2][3]=fmaf(a.z,w.w,acc[2][3]);
            acc[3][0]=fmaf(a.w,w.x,acc[3][0]); acc[3][1]=fmaf(a.w,w.y,acc[3][1]);
            acc[3][2]=fmaf(a.w,w.z,acc[3][2]); acc[3][3]=fmaf(a.w,w.w,acc[3][3]);
            w = wn; a = an;
        }
    }
    float bias[4] = {0.f,0.f,0.f,0.f};
    if (b0){
        #pragma unroll
        for (int j=0;j<4;j++) bias[j] += b0[col0+j];
    }
    if (b1){
        #pragma unroll
        for (int j=0;j<4;j++) bias[j] += b1[col0+j];
    }
    #pragma unroll
    for (int i=0;i<4;i++){
        #pragma unroll
        for (int j=0;j<4;j++){
            acc[i][j] += bias[j];
            if (act) acc[i][j] = tanhf(acc[i][j]);
        }
    }
    if (doLN){
        #pragma unroll
        for (int i=0;i<4;i++){
            float s = acc[i][0]+acc[i][1]+acc[i][2]+acc[i][3];
            #pragma unroll
            for (int o = 16; o > 0; o >>= 1) s += __shfl_xor_sync(0xffffffffu, s, o);
            float mean = s * (1.f/HID);
            float d0 = acc[i][0]-mean, d1 = acc[i][1]-mean,
                  d2 = acc[i][2]-mean, d3 = acc[i][3]-mean;
            float q = d0*d0 + d1*d1 + d2*d2 + d3*d3;
            #pragma unroll
            for (int o = 16; o > 0; o >>= 1) q += __shfl_xor_sync(0xffffffffu, q, o);
            float inv = 1.0f / sqrtf(q * (1.f/HID) + 1e-5f);
            acc[i][0] = d0*inv; acc[i][1] = d1*inv;
            acc[i][2] = d2*inv; acc[i][3] = d3*inv;
        }
    }
    #pragma unroll
    for (int i=0;i<4;i++){
        int r = row0 + ty*4 + i;
        float4 o;
        o.x = acc[i][0]; o.y = acc[i][1]; o.z = acc[i][2]; o.w = acc[i][3];
        *reinterpret_cast<float4*>(C + (size_t)r*HID + col0) = o;
    }
}

// ---------------- GAT: warp-per-(node,batch); no block barriers ----------------
__global__ void __launch_bounds__(256) k_gat(
    const float* __restrict__ hp, const float* __restrict__ el,
    const float* __restrict__ er,
    const int* __restrict__ off, const int* __restrict__ eidx,
    const int* __restrict__ src, float* __restrict__ kout,
    const float* __restrict__ yin, const float* __restrict__ k1,
    const float* __restrict__ k2, const float* __restrict__ k3, float dtc)
{
    const unsigned FULL = 0xffffffffu;
    int n    = blockIdx.x;
    int b    = threadIdx.x >> 5;
    int lane = threadIdx.x & 31;
    int bn   = b*NN + n;

    const float* hb  = hp + (size_t)b*NN*HID;
    const float* elb = el + (size_t)b*NN*HEADS;

    float erv[8];
    {
        float4 e0v = *reinterpret_cast<const float4*>(er + (size_t)bn*HEADS);
        float4 e1v = *reinterpret_cast<const float4*>(er + (size_t)bn*HEADS + 4);
        erv[0]=e0v.x; erv[1]=e0v.y; erv[2]=e0v.z; erv[3]=e0v.w;
        erv[4]=e1v.x; erv[5]=e1v.y; erv[6]=e1v.z; erv[7]=e1v.w;
    }

    int e0 = off[n], deg = off[n+1] - e0;

    float acc[4] = {0.f,0.f,0.f,0.f};
    float m[8], ssum[8];
    #pragma unroll
    for (int h=0;h<8;h++){ m[h] = -FLT_MAX; ssum[h] = 0.f; }

    for (int base = 0; base < deg; base += 32){
        int cnt = min(32, deg - base);
        int sj = 0;
        float lg[8];
        if (lane < cnt){
            sj = src[eidx[e0 + base + lane]];
            float4 v0 = *reinterpret_cast<const float4*>(elb + (size_t)sj*HEADS);
            float4 v1 = *reinterpret_cast<const float4*>(elb + (size_t)sj*HEADS + 4);
            float t0;
            t0 = v0.x + erv[0]; lg[0] = (t0>=0.f)?t0:0.2f*t0;
            t0 = v0.y + erv[1]; lg[1] = (t0>=0.f)?t0:0.2f*t0;
            t0 = v0.z + erv[2]; lg[2] = (t0>=0.f)?t0:0.2f*t0;
            t0 = v0.w + erv[3]; lg[3] = (t0>=0.f)?t0:0.2f*t0;
            t0 = v1.x + erv[4]; lg[4] = (t0>=0.f)?t0:0.2f*t0;
            t0 = v1.y + erv[5]; lg[5] = (t0>=0.f)?t0:0.2f*t0;
            t0 = v1.z + erv[6]; lg[6] = (t0>=0.f)?t0:0.2f*t0;
            t0 = v1.w + erv[7]; lg[7] = (t0>=0.f)?t0:0.2f*t0;
        } else {
            #pragma unroll
            for (int h=0;h<8;h++) lg[h] = -FLT_MAX;
        }
        float nm[8];
        #pragma unroll
        for (int h=0;h<8;h++) nm[h] = lg[h];
        #pragma unroll
        for (int o = 16; o > 0; o >>= 1){
            #pragma unroll
            for (int h=0;h<8;h++)
                nm[h] = fmaxf(nm[h], __shfl_xor_sync(FULL, nm[h], o));
        }
        float w[8], sc[8];
        #pragma unroll
        for (int h=0;h<8;h++){
            float newm = fmaxf(m[h], nm[h]);
            sc[h] = (m[h] == -FLT_MAX) ? 0.f : __expf(m[h] - newm);
            m[h]  = newm;
            w[h]  = __expf(lg[h] - newm);
        }
        if (base > 0){
            #pragma unroll
            for (int g=0;g<4;g++){
                float s01 = (lane < 16) ? sc[2*g] : sc[2*g+1];
                acc[g] *= s01;
            }
            #pragma unroll
            for (int h=0;h<8;h++) ssum[h] *= sc[h];
        }
        float cs[8];
        #pragma unroll
        for (int h=0;h<8;h++) cs[h] = w[h];
        #pragma unroll
        for (int o = 16; o > 0; o >>= 1){
            #pragma unroll
            for (int h=0;h<8;h++)
                cs[h] += __shfl_xor_sync(FULL, cs[h], o);
        }
        #pragma unroll
        for (int h=0;h<8;h++) ssum[h] += cs[h];
        for (int j = 0; j < cnt; j++){
            int s = __shfl_sync(FULL, sj, j);
            const float* hr = hb + (size_t)s*HID;
            #pragma unroll
            for (int g=0;g<4;g++){
                float wa = __shfl_sync(FULL, w[2*g],   j);
                float wb = __shfl_sync(FULL, w[2*g+1], j);
                float ww = (lane < 16) ? wa : wb;
                acc[g] = fmaf(ww, hr[lane + 32*g], acc[g]);
            }
        }
    }
    #pragma unroll
    for (int g=0;g<4;g++){
        float s = ((lane < 16) ? ssum[2*g] : ssum[2*g+1]) + 1e-16f;
        float kv = acc[g] / s;
        size_t o = (size_t)bn*HID + lane + 32*g;
        if (yin){
            kout[o] = yin[o] + dtc*(k1[o] + 2.f*k2[o] + 2.f*k3[o] + kv);
        } else {
            kout[o] = kv;
        }
    }
}

// ---------------- LayerNorm (idx==0 only) ----------------
__global__ void __launch_bounds__(128) k_ln(const float* __restrict__ s, float* __restrict__ d){
    int row = blockIdx.x;
    int t = threadIdx.x;
    __shared__ float sh[4];
    float v = s[(size_t)row*HID + t];

    float a = v;
    #pragma unroll
    for (int o = 16; o > 0; o >>= 1) a += __shfl_xor_sync(0xffffffffu, a, o);
    if ((t & 31) == 0) sh[t >> 5] = a;
    __syncthreads();
    float mean = (sh[0]+sh[1]+sh[2]+sh[3]) * (1.f/HID);

    float dv = v - mean;
    float q = dv*dv;
    __syncthreads();
    #pragma unroll
    for (int o = 16; o > 0; o >>= 1) q += __shfl_xor_sync(0xffffffffu, q, o);
    if ((t & 31) == 0) sh[t >> 5] = q;
    __syncthreads();
    float var = (sh[0]+sh[1]+sh[2]+sh[3]) * (1.f/HID);

    d[(size_t)row*HID + t] = dv / sqrtf(var + 1e-5f);
}

// ---------------- launch ----------------
extern "C" void kernel_launch(void* const* d_in, const int* in_sizes, int n_in,
                              void* d_out, int out_size)
{
    const float* inputs = (const float*)d_in[0];
    const int*   src    = (const int*)  d_in[1];
    const int*   dst    = (const int*)  d_in[2];
    const float* w_in   = (const float*)d_in[3];
    const float* b_in   = (const float*)d_in[4];
    const float* w_gat  = (const float*)d_in[5];
    const float* a_l    = (const float*)d_in[6];
    const float* a_r    = (const float*)d_in[7];
    const float* w_W    = (const float*)d_in[8];
    const float* b_W    = (const float*)d_in[9];
    const float* w_U    = (const float*)d_in[10];
    const float* b_U    = (const float*)d_in[11];
    const float* w_o1   = (const float*)d_in[12];
    const float* b_o1   = (const float*)d_in[13];
    const float* w_o2   = (const float*)d_in[14];
    const float* b_o2   = (const float*)d_in[15];
    float* out = (float*)d_out;

    float *hin, *y, *hp, *k1, *k2, *k3, *tmp, *el, *er;
    unsigned *whi, *wlo;
    int *cnt, *cur, *off, *eidx;
    cudaGetSymbolAddress((void**)&hin, g_hin);
    cudaGetSymbolAddress((void**)&y,   g_y);
    cudaGetSymbolAddress((void**)&hp,  g_hp);
    cudaGetSymbolAddress((void**)&k1,  g_k1);
    cudaGetSymbolAddress((void**)&k2,  g_k2);
    cudaGetSymbolAddress((void**)&k3,  g_k3);
    cudaGetSymbolAddress((void**)&tmp, g_tmp);
    cudaGetSymbolAddress((void**)&el,  g_el);
    cudaGetSymbolAddress((void**)&er,  g_er);
    cudaGetSymbolAddress((void**)&whi, g_whi);
    cudaGetSymbolAddress((void**)&wlo, g_wlo);
    cudaGetSymbolAddress((void**)&cnt, g_cnt);
    cudaGetSymbolAddress((void**)&cur, g_cur);
    cudaGetSymbolAddress((void**)&off, g_off);
    cudaGetSymbolAddress((void**)&eidx,g_eidx);

    const float* F0 = (const float*)0;

    static bool attr_set = false;
    if (!attr_set){
        cudaFuncSetAttribute(k_gemm,     cudaFuncAttributeMaxDynamicSharedMemorySize, GEMM_SMEM);
        cudaFuncSetAttribute(k_gemm_mma, cudaFuncAttributeMaxDynamicSharedMemorySize, MMA_SMEM);
        attr_set = true;
    }

    const float dt  = 0.25f;
    const float dtc = dt / 6.0f;

    // prelude
    k_init     <<<B*SEQ*NN, HID>>>(inputs, w_in, b_in, hin, y, cnt, cur);
    k_wsplit   <<<(HID*HID+255)/256, 256>>>(w_gat, whi, wlo);
    k_csr_count<<<(E+255)/256, 256>>>(dst, cnt);
    k_csr_scan <<<1, 1024>>>(cnt, off);

    // first RK4 stage-1 GEMM (does not need CSR) — lands at ncu -s 5 slot
    k_gemm_mma<<<125,512,MMA_SMEM>>>(y, F0, 0.f, whi, wlo, hp, el, er, a_l, a_r);

    k_csr_fill <<<(E+255)/256, 256>>>(dst, off, cur, eidx);
    k_csr_sort <<<NN, 32>>>(off, eidx);

    for (int idx = 0; idx < SEQ; idx++){
        for (int s = 0; s < 4; s++){
            if (!(idx == 0 && s == 0)){
                k_gemm_mma<<<125,512,MMA_SMEM>>>(y, F0, 0.f, whi, wlo, hp, el, er, a_l, a_r);
            }
            k_gat <<<NN,256>>>(hp, el, er, off, eidx, src, k1, F0,F0,F0,F0, 0.f);
            k_gemm_mma<<<125,512,MMA_SMEM>>>(y, k1, 0.5f*dt, whi, wlo, hp, el, er, a_l, a_r);
            k_gat <<<NN,256>>>(hp, el, er, off, eidx, src, k2, F0,F0,F0,F0, 0.f);
            k_gemm_mma<<<125,512,MMA_SMEM>>>(y, k2, 0.5f*dt, whi, wlo, hp, el, er, a_l, a_r);
            k_gat <<<NN,256>>>(hp, el, er, off, eidx, src, k3, F0,F0,F0,F0, 0.f);
            k_gemm_mma<<<125,512,MMA_SMEM>>>(y, k3, dt, whi, wlo, hp, el, er, a_l, a_r);
            k_gat <<<NN,256>>>(hp, el, er, off, eidx, src, y, y, k1, k2, k3, dtc);
        }
        if (idx > 0){
            // y = LN(tanh(y@w_W + h[idx]@w_U + b_W + b_U)) — LN fused (FFMA path)
            const float* hidx = hin + (size_t)idx * M_ROWS * HID;
            k_gemm<<<125,512,GEMM_SMEM>>>(y, F0, 0.f, w_W, hidx, w_U, b_W, b_U, y, 1,1);
        } else {
            k_ln  <<<M_ROWS,128>>>(y, y);
        }
    }

    // out = tanh(y@w_o1 + b_o1) @ w_o2 + b_o2  (FFMA path)
    k_gemm<<<125,512,GEMM_SMEM>>>(y,   F0, 0.f, w_o1, F0,F0, b_o1,F0, tmp, 1,0);
    k_gemm<<<125,512,GEMM_SMEM>>>(tmp, F0, 0.f, w_o2, F0,F0, b_o2,F0, out, 0,0);
}

// round 13
// speedup vs baseline: 1.0507x; 1.0507x over previous
#include <cuda_runtime.h>
#include <cuda_fp16.h>
#include <math.h>
#include <float.h>

#define B 8
#define SEQ 12
#define NN 1000
#define E 16000
#define HID 128
#define HEADS 8
#define DH 16
#define M_ROWS (B*NN)          /* 8000 */

#define AT_STRIDE 68           /* 64 rows + 4 pad (floats) */
#define GEMM_SMEM (HID*HID*4 + HID*AT_STRIDE*4)   /* 64KB W + 34KB A^T */

// ---------------- static device scratch ----------------
__device__ float  g_hin[(size_t)SEQ*B*NN*HID];   // [SEQ][B][N][HID]
__device__ float  g_y  [(size_t)M_ROWS*HID];
__device__ __half g_hp [(size_t)M_ROWS*HID];     // fp16 GAT features
__device__ float  g_k1 [(size_t)M_ROWS*HID];
__device__ float  g_k2 [(size_t)M_ROWS*HID];
__device__ float  g_k3 [(size_t)M_ROWS*HID];
__device__ float  g_tmp[(size_t)M_ROWS*HID];
__device__ float  g_el [(size_t)M_ROWS*HEADS];
__device__ float  g_er [(size_t)M_ROWS*HEADS];
__device__ int    g_cnt[NN];
__device__ int    g_cur[NN];
__device__ int    g_off[NN+1];
__device__ int    g_eidx[E];
__device__ int    g_srcs[E];                     // CSR-ordered source ids

// ---------------- fused init: inproj + y=h[:,0] + CSR zero ----------------
__global__ void k_init(const float* __restrict__ inp, const float* __restrict__ w_in,
                       const float* __restrict__ b_in, float* __restrict__ hin,
                       float* __restrict__ y, int* cnt, int* cur){
    int row = blockIdx.x;
    int t = threadIdx.x;
    if (blockIdx.x < 8){
        int q = blockIdx.x*128 + t;
        if (q < NN){ cnt[q] = 0; cur[q] = 0; }
    }
    int b = row / (SEQ*NN);
    int s = (row / NN) % SEQ;
    int n = row % NN;
    float x0 = inp[(size_t)row*2 + 0];
    float x1 = inp[(size_t)row*2 + 1];
    float v = fmaf(x0, w_in[t], fmaf(x1, w_in[HID+t], b_in[t]));
    hin[(((size_t)s*B + b)*NN + n)*HID + t] = v;
    if (s == 0) y[((size_t)b*NN + n)*HID + t] = v;
}

// ---------------- CSR construction (deterministic) ----------------
__global__ void k_csr_count(const int* __restrict__ dst, int* cnt){
    int e = blockIdx.x*blockDim.x + threadIdx.x;
    if (e < E) atomicAdd(&cnt[dst[e]], 1);
}
__global__ void k_csr_scan(const int* __restrict__ cnt, int* off){
    __shared__ int s[1024];
    int t = threadIdx.x;
    s[t] = (t < NN) ? cnt[t] : 0;
    __syncthreads();
    #pragma unroll
    for (int o = 1; o < 1024; o <<= 1){
        int v = (t >= o) ? s[t-o] : 0;
        __syncthreads();
        s[t] += v;
        __syncthreads();
    }
    if (t == 0) off[0] = 0;
    if (t < NN) off[t+1] = s[t];
}
__global__ void k_csr_fill(const int* __restrict__ dst, const int* __restrict__ off,
                           int* cur, int* eidx){
    int e = blockIdx.x*blockDim.x + threadIdx.x;
    if (e < E){
        int d = dst[e];
        int p = atomicAdd(&cur[d], 1);
        eidx[off[d] + p] = e;
    }
}
__global__ void k_csr_sort(const int* __restrict__ off, int* eidx){
    if (threadIdx.x != 0) return;
    int n = blockIdx.x;
    int a = off[n], b = off[n+1];
    for (int i = a+1; i < b; i++){
        int v = eidx[i]; int j = i-1;
        while (j >= a && eidx[j] > v){ eidx[j+1] = eidx[j]; j--; }
        eidx[j+1] = v;
    }
}
__global__ void k_csr_gather(const int* __restrict__ eidx, const int* __restrict__ src,
                             int* __restrict__ srcs){
    int i = blockIdx.x*blockDim.x + threadIdx.x;
    if (i < E) srcs[i] = src[eidx[i]];
}

// ---------------- GEMM: C = act( (A0 + c1*A1)@W0 [+ A2@W1] + b0 + b1 ) --------
// 64 rows x 128 cols per block, grid 125, 512 threads (4x4 tile). SW-pipelined
// all-smem inner loop. If Ch != 0: store fp16 to Ch (GAT path) else fp32 to C.
// One warp owns complete rows -> fused LN (doLN). Optional el/er GAT epilogue.
__global__ void __launch_bounds__(512) k_gemm(
    const float* __restrict__ A0, const float* __restrict__ A1, float c1,
    const float* __restrict__ W0,
    const float* __restrict__ A2, const float* __restrict__ W1,
    const float* __restrict__ b0, const float* __restrict__ b1,
    float* __restrict__ C, __half* __restrict__ Ch, int act, int doLN,
    float* __restrict__ el, float* __restrict__ er,
    const float* __restrict__ a_l, const float* __restrict__ a_r)
{
    extern __shared__ float smem[];
    float* sW  = smem;                 // [128][128]
    float* sAT = smem + HID*HID;       // [128][AT_STRIDE]

    int row0 = blockIdx.x * 64;
    int tid = threadIdx.x;
    int tx = tid & 31, ty = tid >> 5;  // lane: 4 cols; warp(0..15): 4 rows
    int col0 = tx * 4;

    float acc[4][4];
    #pragma unroll
    for (int i=0;i<4;i++)
        #pragma unroll
        for (int j=0;j<4;j++) acc[i][j] = 0.f;

    // ---- stage W0 ----
    {
        const float4* W4 = (const float4*)W0;
        float4* sW4 = (float4*)sW;
        #pragma unroll
        for (int i = tid; i < HID*32; i += 512) sW4[i] = W4[i];
    }
    // ---- stage A tile transposed (with fused axpy) ----
    {
        const float4* A04 = (const float4*)A0;
        const float4* A14 = (const float4*)A1;
        #pragma unroll
        for (int i = tid; i < 64*32; i += 512){
            int r = i >> 5, c4 = i & 31;
            float4 v = A04[(size_t)(row0+r)*32 + c4];
            if (A1){
                float4 u = A14[(size_t)(row0+r)*32 + c4];
                v.x = fmaf(c1,u.x,v.x); v.y = fmaf(c1,u.y,v.y);
                v.z = fmaf(c1,u.z,v.z); v.w = fmaf(c1,u.w,v.w);
            }
            int k0 = c4*4;
            sAT[(k0+0)*AT_STRIDE + r] = v.x;
            sAT[(k0+1)*AT_STRIDE + r] = v.y;
            sAT[(k0+2)*AT_STRIDE + r] = v.z;
            sAT[(k0+3)*AT_STRIDE + r] = v.w;
        }
    }
    __syncthreads();
    // ---- product 0: software-pipelined all-smem inner loop ----
    {
        const float4* sW4 = (const float4*)sW;
        float4 w = sW4[tx];
        float4 a = *reinterpret_cast<const float4*>(sAT + ty*4);
        #pragma unroll 4
        for (int k = 0; k < HID; k++){
            int kn = (k+1) & 127;
            float4 wn = sW4[kn*32 + tx];
            float4 an = *reinterpret_cast<const float4*>(sAT + kn*AT_STRIDE + ty*4);
            acc[0][0]=fmaf(a.x,w.x,acc[0][0]); acc[0][1]=fmaf(a.x,w.y,acc[0][1]);
            acc[0][2]=fmaf(a.x,w.z,acc[0][2]); acc[0][3]=fmaf(a.x,w.w,acc[0][3]);
            acc[1][0]=fmaf(a.y,w.x,acc[1][0]); acc[1][1]=fmaf(a.y,w.y,acc[1][1]);
            acc[1][2]=fmaf(a.y,w.z,acc[1][2]); acc[1][3]=fmaf(a.y,w.w,acc[1][3]);
            acc[2][0]=fmaf(a.z,w.x,acc[2][0]); acc[2][1]=fmaf(a.z,w.y,acc[2][1]);
            acc[2][2]=fmaf(a.z,w.z,acc[2][2]); acc[2][3]=fmaf(a.z,w.w,acc[2][3]);
            acc[3][0]=fmaf(a.w,w.x,acc[3][0]); acc[3][1]=fmaf(a.w,w.y,acc[3][1]);
            acc[3][2]=fmaf(a.w,w.z,acc[3][2]); acc[3][3]=fmaf(a.w,w.w,acc[3][3]);
            w = wn; a = an;
        }
    }
    // ---- optional product 1 ----
    if (A2){
        __syncthreads();
        {
            const float4* W4 = (const float4*)W1;
            float4* sW4 = (float4*)sW;
            #pragma unroll
            for (int i = tid; i < HID*32; i += 512) sW4[i] = W4[i];
            const float4* A24 = (const float4*)A2;
            #pragma unroll
            for (int i = tid; i < 64*32; i += 512){
                int r = i >> 5, c4 = i & 31;
                float4 v = A24[(size_t)(row0+r)*32 + c4];
                int k0 = c4*4;
                sAT[(k0+0)*AT_STRIDE + r] = v.x;
                sAT[(k0+1)*AT_STRIDE + r] = v.y;
                sAT[(k0+2)*AT_STRIDE + r] = v.z;
                sAT[(k0+3)*AT_STRIDE + r] = v.w;
            }
        }
        __syncthreads();
        const float4* sW4 = (const float4*)sW;
        float4 w = sW4[tx];
        float4 a = *reinterpret_cast<const float4*>(sAT + ty*4);
        #pragma unroll 4
        for (int k = 0; k < HID; k++){
            int kn = (k+1) & 127;
            float4 wn = sW4[kn*32 + tx];
            float4 an = *reinterpret_cast<const float4*>(sAT + kn*AT_STRIDE + ty*4);
            acc[0][0]=fmaf(a.x,w.x,acc[0][0]); acc[0][1]=fmaf(a.x,w.y,acc[0][1]);
            acc[0][2]=fmaf(a.x,w.z,acc[0][2]); acc[0][3]=fmaf(a.x,w.w,acc[0][3]);
            acc[1][0]=fmaf(a.y,w.x,acc[1][0]); acc[1][1]=fmaf(a.y,w.y,acc[1][1]);
            acc[1][2]=fmaf(a.y,w.z,acc[1][2]); acc[1][3]=fmaf(a.y,w.w,acc[1][3]);
            acc[2][0]=fmaf(a.z,w.x,acc[2][0]); acc[2][1]=fmaf(a.z,w.y,acc[2][1]);
            acc[2][2]=fmaf(a.z,w.z,acc[2][2]); acc[2][3]=fmaf(a.z,w.w,acc[2][3]);
            acc[3][0]=fmaf(a.w,w.x,acc[3][0]); acc[3][1]=fmaf(a.w,w.y,acc[3][1]);
            acc[3][2]=fmaf(a.w,w.z,acc[3][2]); acc[3][3]=fmaf(a.w,w.w,acc[3][3]);
            w = wn; a = an;
        }
    }
    // ---- bias + activation ----
    float bias[4] = {0.f,0.f,0.f,0.f};
    if (b0){
        #pragma unroll
        for (int j=0;j<4;j++) bias[j] += b0[col0+j];
    }
    if (b1){
        #pragma unroll
        for (int j=0;j<4;j++) bias[j] += b1[col0+j];
    }
    #pragma unroll
    for (int i=0;i<4;i++){
        #pragma unroll
        for (int j=0;j<4;j++){
            acc[i][j] += bias[j];
            if (act) acc[i][j] = tanhf(acc[i][j]);
        }
    }
    // ---- optional fused LayerNorm ----
    if (doLN){
        #pragma unroll
        for (int i=0;i<4;i++){
            float s = acc[i][0]+acc[i][1]+acc[i][2]+acc[i][3];
            #pragma unroll
            for (int o = 16; o > 0; o >>= 1) s += __shfl_xor_sync(0xffffffffu, s, o);
            float mean = s * (1.f/HID);
            float d0 = acc[i][0]-mean, d1 = acc[i][1]-mean,
                  d2 = acc[i][2]-mean, d3 = acc[i][3]-mean;
            float q = d0*d0 + d1*d1 + d2*d2 + d3*d3;
            #pragma unroll
            for (int o = 16; o > 0; o >>= 1) q += __shfl_xor_sync(0xffffffffu, q, o);
            float inv = 1.0f / sqrtf(q * (1.f/HID) + 1e-5f);
            acc[i][0] = d0*inv; acc[i][1] = d1*inv;
            acc[i][2] = d2*inv; acc[i][3] = d3*inv;
        }
    }
    // ---- store: fp16 (GAT path) or fp32 ----
    if (Ch){
        #pragma unroll
        for (int i=0;i<4;i++){
            int r = row0 + ty*4 + i;
            __half2 p[2];
            p[0] = __floats2half2_rn(acc[i][0], acc[i][1]);
            p[1] = __floats2half2_rn(acc[i][2], acc[i][3]);
            *reinterpret_cast<uint2*>(Ch + (size_t)r*HID + col0) =
                *reinterpret_cast<uint2*>(p);
        }
    } else {
        #pragma unroll
        for (int i=0;i<4;i++){
            int r = row0 + ty*4 + i;
            float4 o;
            o.x = acc[i][0]; o.y = acc[i][1]; o.z = acc[i][2]; o.w = acc[i][3];
            *reinterpret_cast<float4*>(C + (size_t)r*HID + col0) = o;
        }
    }
    // ---- GAT logit epilogue (fp32 acc; head = tx>>2) ----
    if (el){
        int head  = tx >> 2;
        int dbase = (tx & 3) * 4;
        #pragma unroll
        for (int i=0;i<4;i++){
            float pl = 0.f, pr = 0.f;
            #pragma unroll
            for (int j=0;j<4;j++){
                pl = fmaf(acc[i][j], a_l[head*DH + dbase + j], pl);
                pr = fmaf(acc[i][j], a_r[head*DH + dbase + j], pr);
            }
            pl += __shfl_xor_sync(0xffffffffu, pl, 1);
            pl += __shfl_xor_sync(0xffffffffu, pl, 2);
            pr += __shfl_xor_sync(0xffffffffu, pr, 1);
            pr += __shfl_xor_sync(0xffffffffu, pr, 2);
            if ((tx & 3) == 0){
                int r = row0 + ty*4 + i;
                el[(size_t)r*HEADS + head] = pl;
                er[(size_t)r*HEADS + head] = pr;
            }
        }
    }
}

// ---------------- GAT: warp-per-(node,batch); fp16 feature gather ----------------
__global__ void __launch_bounds__(256) k_gat(
    const __half* __restrict__ hp, const float* __restrict__ el,
    const float* __restrict__ er,
    const int* __restrict__ off, const int* __restrict__ srcs,
    float* __restrict__ kout,
    const float* __restrict__ yin, const float* __restrict__ k1,
    const float* __restrict__ k2, const float* __restrict__ k3, float dtc)
{
    const unsigned FULL = 0xffffffffu;
    int n    = blockIdx.x;
    int b    = threadIdx.x >> 5;
    int lane = threadIdx.x & 31;
    int bn   = b*NN + n;

    const __half* hb  = hp + (size_t)b*NN*HID;
    const float*  elb = el + (size_t)b*NN*HEADS;

    float erv[8];
    {
        float4 e0v = *reinterpret_cast<const float4*>(er + (size_t)bn*HEADS);
        float4 e1v = *reinterpret_cast<const float4*>(er + (size_t)bn*HEADS + 4);
        erv[0]=e0v.x; erv[1]=e0v.y; erv[2]=e0v.z; erv[3]=e0v.w;
        erv[4]=e1v.x; erv[5]=e1v.y; erv[6]=e1v.z; erv[7]=e1v.w;
    }

    int e0 = off[n], deg = off[n+1] - e0;

    float acc[4] = {0.f,0.f,0.f,0.f};
    float m[8], ssum[8];
    #pragma unroll
    for (int h=0;h<8;h++){ m[h] = -FLT_MAX; ssum[h] = 0.f; }

    for (int base = 0; base < deg; base += 32){
        int cnt = min(32, deg - base);
        int sj = 0;
        float lg[8];
        if (lane < cnt){
            sj = srcs[e0 + base + lane];
            float4 v0 = *reinterpret_cast<const float4*>(elb + (size_t)sj*HEADS);
            float4 v1 = *reinterpret_cast<const float4*>(elb + (size_t)sj*HEADS + 4);
            float t0;
            t0 = v0.x + erv[0]; lg[0] = (t0>=0.f)?t0:0.2f*t0;
            t0 = v0.y + erv[1]; lg[1] = (t0>=0.f)?t0:0.2f*t0;
            t0 = v0.z + erv[2]; lg[2] = (t0>=0.f)?t0:0.2f*t0;
            t0 = v0.w + erv[3]; lg[3] = (t0>=0.f)?t0:0.2f*t0;
            t0 = v1.x + erv[4]; lg[4] = (t0>=0.f)?t0:0.2f*t0;
            t0 = v1.y + erv[5]; lg[5] = (t0>=0.f)?t0:0.2f*t0;
            t0 = v1.z + erv[6]; lg[6] = (t0>=0.f)?t0:0.2f*t0;
            t0 = v1.w + erv[7]; lg[7] = (t0>=0.f)?t0:0.2f*t0;
        } else {
            #pragma unroll
            for (int h=0;h<8;h++) lg[h] = -FLT_MAX;
        }
        float nm[8];
        #pragma unroll
        for (int h=0;h<8;h++) nm[h] = lg[h];
        #pragma unroll
        for (int o = 16; o > 0; o >>= 1){
            #pragma unroll
            for (int h=0;h<8;h++)
                nm[h] = fmaxf(nm[h], __shfl_xor_sync(FULL, nm[h], o));
        }
        float w[8], sc[8];
        #pragma unroll
        for (int h=0;h<8;h++){
            float newm = fmaxf(m[h], nm[h]);
            sc[h] = (m[h] == -FLT_MAX) ? 0.f : __expf(m[h] - newm);
            m[h]  = newm;
            w[h]  = __expf(lg[h] - newm);
        }
        if (base > 0){
            #pragma unroll
            for (int g=0;g<4;g++){
                float s01 = (lane < 16) ? sc[2*g] : sc[2*g+1];
                acc[g] *= s01;
            }
            #pragma unroll
            for (int h=0;h<8;h++) ssum[h] *= sc[h];
        }
        float cs[8];
        #pragma unroll
        for (int h=0;h<8;h++) cs[h] = w[h];
        #pragma unroll
        for (int o = 16; o > 0; o >>= 1){
            #pragma unroll
            for (int h=0;h<8;h++)
                cs[h] += __shfl_xor_sync(FULL, cs[h], o);
        }
        #pragma unroll
        for (int h=0;h<8;h++) ssum[h] += cs[h];
        for (int j = 0; j < cnt; j++){
            int s = __shfl_sync(FULL, sj, j);
            const __half* hr = hb + (size_t)s*HID;
            float h0 = __half2float(hr[lane]);
            float h1 = __half2float(hr[lane + 32]);
            float h2 = __half2float(hr[lane + 64]);
            float h3 = __half2float(hr[lane + 96]);
            float w0 = __shfl_sync(FULL, w[0], j);
            float w1 = __shfl_sync(FULL, w[1], j);
            float w2 = __shfl_sync(FULL, w[2], j);
            float w3 = __shfl_sync(FULL, w[3], j);
            float w4 = __shfl_sync(FULL, w[4], j);
            float w5 = __shfl_sync(FULL, w[5], j);
            float w6 = __shfl_sync(FULL, w[6], j);
            float w7 = __shfl_sync(FULL, w[7], j);
            bool lo = (lane < 16);
            acc[0] = fmaf(lo ? w0 : w1, h0, acc[0]);
            acc[1] = fmaf(lo ? w2 : w3, h1, acc[1]);
            acc[2] = fmaf(lo ? w4 : w5, h2, acc[2]);
            acc[3] = fmaf(lo ? w6 : w7, h3, acc[3]);
        }
    }
    #pragma unroll
    for (int g=0;g<4;g++){
        float s = ((lane < 16) ? ssum[2*g] : ssum[2*g+1]) + 1e-16f;
        float kv = acc[g] / s;
        size_t o = (size_t)bn*HID + lane + 32*g;
        if (yin){
            kout[o] = yin[o] + dtc*(k1[o] + 2.f*k2[o] + 2.f*k3[o] + kv);
        } else {
            kout[o] = kv;
        }
    }
}

// ---------------- LayerNorm (idx==0 only) ----------------
__global__ void __launch_bounds__(128) k_ln(const float* __restrict__ s, float* __restrict__ d){
    int row = blockIdx.x;
    int t = threadIdx.x;
    __shared__ float sh[4];
    float v = s[(size_t)row*HID + t];

    float a = v;
    #pragma unroll
    for (int o = 16; o > 0; o >>= 1) a += __shfl_xor_sync(0xffffffffu, a, o);
    if ((t & 31) == 0) sh[t >> 5] = a;
    __syncthreads();
    float mean = (sh[0]+sh[1]+sh[2]+sh[3]) * (1.f/HID);

    float dv = v - mean;
    float q = dv*dv;
    __syncthreads();
    #pragma unroll
    for (int o = 16; o > 0; o >>= 1) q += __shfl_xor_sync(0xffffffffu, q, o);
    if ((t & 31) == 0) sh[t >> 5] = q;
    __syncthreads();
    float var = (sh[0]+sh[1]+sh[2]+sh[3]) * (1.f/HID);

    d[(size_t)row*HID + t] = dv / sqrtf(var + 1e-5f);
}

// ---------------- launch ----------------
extern "C" void kernel_launch(void* const* d_in, const int* in_sizes, int n_in,
                              void* d_out, int out_size)
{
    const float* inputs = (const float*)d_in[0];
    const int*   src    = (const int*)  d_in[1];
    const int*   dst    = (const int*)  d_in[2];
    const float* w_in   = (const float*)d_in[3];
    const float* b_in   = (const float*)d_in[4];
    const float* w_gat  = (const float*)d_in[5];
    const float* a_l    = (const float*)d_in[6];
    const float* a_r    = (const float*)d_in[7];
    const float* w_W    = (const float*)d_in[8];
    const float* b_W    = (const float*)d_in[9];
    const float* w_U    = (const float*)d_in[10];
    const float* b_U    = (const float*)d_in[11];
    const float* w_o1   = (const float*)d_in[12];
    const float* b_o1   = (const float*)d_in[13];
    const float* w_o2   = (const float*)d_in[14];
    const float* b_o2   = (const float*)d_in[15];
    float* out = (float*)d_out;

    float *hin, *y, *k1, *k2, *k3, *tmp, *el, *er;
    __half *hp;
    int *cnt, *cur, *off, *eidx, *srcs;
    cudaGetSymbolAddress((void**)&hin, g_hin);
    cudaGetSymbolAddress((void**)&y,   g_y);
    cudaGetSymbolAddress((void**)&hp,  g_hp);
    cudaGetSymbolAddress((void**)&k1,  g_k1);
    cudaGetSymbolAddress((void**)&k2,  g_k2);
    cudaGetSymbolAddress((void**)&k3,  g_k3);
    cudaGetSymbolAddress((void**)&tmp, g_tmp);
    cudaGetSymbolAddress((void**)&el,  g_el);
    cudaGetSymbolAddress((void**)&er,  g_er);
    cudaGetSymbolAddress((void**)&cnt, g_cnt);
    cudaGetSymbolAddress((void**)&cur, g_cur);
    cudaGetSymbolAddress((void**)&off, g_off);
    cudaGetSymbolAddress((void**)&eidx,g_eidx);
    cudaGetSymbolAddress((void**)&srcs,g_srcs);

    const float* F0 = (const float*)0;
    float*       FW = (float*)0;
    __half*      H0 = (__half*)0;

    static bool attr_set = false;
    if (!attr_set){
        cudaFuncSetAttribute(k_gemm, cudaFuncAttributeMaxDynamicSharedMemorySize, GEMM_SMEM);
        attr_set = true;
    }

    const float dt  = 0.25f;
    const float dtc = dt / 6.0f;

    // prelude
    k_init      <<<B*SEQ*NN, HID>>>(inputs, w_in, b_in, hin, y, cnt, cur);
    k_csr_count <<<(E+255)/256, 256>>>(dst, cnt);
    k_csr_scan  <<<1, 1024>>>(cnt, off);

    // first RK4 stage-1 GEMM (does not need CSR)
    k_gemm<<<125,512,GEMM_SMEM>>>(y, F0, 0.f, w_gat, F0,F0,F0,F0, FW, hp, 0,0, el, er, a_l, a_r);

    k_csr_fill  <<<(E+255)/256, 256>>>(dst, off, cur, eidx);
    k_csr_sort  <<<NN, 32>>>(off, eidx);
    k_csr_gather<<<(E+255)/256, 256>>>(eidx, src, srcs);

    for (int idx = 0; idx < SEQ; idx++){
        for (int s = 0; s < 4; s++){
            if (!(idx == 0 && s == 0)){
                k_gemm<<<125,512,GEMM_SMEM>>>(y, F0, 0.f, w_gat, F0,F0,F0,F0, FW, hp, 0,0, el, er, a_l, a_r);
            }
            k_gat <<<NN,256>>>(hp, el, er, off, srcs, k1, F0,F0,F0,F0, 0.f);
            k_gemm<<<125,512,GEMM_SMEM>>>(y, k1, 0.5f*dt, w_gat, F0,F0,F0,F0, FW, hp, 0,0, el, er, a_l, a_r);
            k_gat <<<NN,256>>>(hp, el, er, off, srcs, k2, F0,F0,F0,F0, 0.f);
            k_gemm<<<125,512,GEMM_SMEM>>>(y, k2, 0.5f*dt, w_gat, F0,F0,F0,F0, FW, hp, 0,0, el, er, a_l, a_r);
            k_gat <<<NN,256>>>(hp, el, er, off, srcs, k3, F0,F0,F0,F0, 0.f);
            k_gemm<<<125,512,GEMM_SMEM>>>(y, k3, dt, w_gat, F0,F0,F0,F0, FW, hp, 0,0, el, er, a_l, a_r);
            k_gat <<<NN,256>>>(hp, el, er, off, srcs, y, y, k1, k2, k3, dtc);
        }
        if (idx > 0){
            // y = LN(tanh(y@w_W + h[idx]@w_U + b_W + b_U)) — LN fused, fp32 store
            const float* hidx = hin + (size_t)idx * M_ROWS * HID;
            k_gemm<<<125,512,GEMM_SMEM>>>(y, F0, 0.f, w_W, hidx, w_U, b_W, b_U, y, H0, 1,1, FW,FW,F0,F0);
        } else {
            k_ln  <<<M_ROWS,128>>>(y, y);
        }
    }

    // out = tanh(y@w_o1 + b_o1) @ w_o2 + b_o2  (fp32 path)
    k_gemm<<<125,512,GEMM_SMEM>>>(y,   F0, 0.f, w_o1, F0,F0, b_o1,F0, tmp, H0, 1,0, FW,FW,F0,F0);
    k_gemm<<<125,512,GEMM_SMEM>>>(tmp, F0, 0.f, w_o2, F0,F0, b_o2,F0, out, H0, 0,0, FW,FW,F0,F0);
}

// round 14
// speedup vs baseline: 1.3117x; 1.2484x over previous
#include <cuda_runtime.h>
#include <cuda_fp16.h>
#include <math.h>
#include <float.h>
#include <stdint.h>

#define B 8
#define SEQ 12
#define NN 1000
#define E 16000
#define HID 128
#define HEADS 8
#define DH 16
#define M_ROWS (B*NN)          /* 8000 */

#define AT_STRIDE 68
#define GEMM_SMEM (HID*HID*4 + HID*AT_STRIDE*4)   /* FFMA gemm */

/* fp16-mma gemm smem (uint32 words), stride 68 words per row */
#define HS 68
#define A_H_OFF 0
#define A_L_OFF (64*HS)
#define B_H_OFF (2*64*HS)
#define B_L_OFF (2*64*HS + 128*HS)
#define HMMA_SMEM ((2*64*HS + 2*128*HS)*4)   /* 104448 B */

// ---------------- static device scratch ----------------
__device__ float    g_hin[(size_t)SEQ*B*NN*HID];
__device__ float    g_y  [(size_t)M_ROWS*HID];
__device__ __half   g_hp [(size_t)M_ROWS*HID];
__device__ float    g_k1 [(size_t)M_ROWS*HID];
__device__ float    g_k2 [(size_t)M_ROWS*HID];
__device__ float    g_k3 [(size_t)M_ROWS*HID];
__device__ float    g_tmp[(size_t)M_ROWS*HID];
__device__ float    g_el [(size_t)M_ROWS*HEADS];
__device__ float    g_er [(size_t)M_ROWS*HEADS];
__device__ unsigned g_wh [HID*HID/2];   /* W^T fp16 hi: [n][kword] */
__device__ unsigned g_wl [HID*HID/2];
__device__ int      g_cnt[NN];
__device__ int      g_cur[NN];
__device__ int      g_off[NN+1];
__device__ int      g_eidx[E];
__device__ int      g_srcs[E];

// ---------------- helpers ----------------
__device__ __forceinline__ unsigned packh2(float a, float b){
    __half2 t = __floats2half2_rn(a, b);
    unsigned u; memcpy(&u, &t, 4); return u;
}
__device__ __forceinline__ float h_res(float x){
    return x - __half2float(__float2half_rn(x));
}
#define HMMA16(c, a0,a1,a2,a3, b0,b1) \
    asm volatile("mma.sync.aligned.m16n8k16.row.col.f32.f16.f16.f32 " \
        "{%0,%1,%2,%3}, {%4,%5,%6,%7}, {%8,%9}, {%0,%1,%2,%3};" \
        : "+f"((c)[0]), "+f"((c)[1]), "+f"((c)[2]), "+f"((c)[3]) \
        : "r"(a0), "r"(a1), "r"(a2), "r"(a3), "r"(b0), "r"(b1))

// ---------------- fused init: inproj + y=h[:,0] + CSR zero ----------------
__global__ void k_init(const float* __restrict__ inp, const float* __restrict__ w_in,
                       const float* __restrict__ b_in, float* __restrict__ hin,
                       float* __restrict__ y, int* cnt, int* cur){
    int row = blockIdx.x;
    int t = threadIdx.x;
    if (blockIdx.x < 8){
        int q = blockIdx.x*128 + t;
        if (q < NN){ cnt[q] = 0; cur[q] = 0; }
    }
    int b = row / (SEQ*NN);
    int s = (row / NN) % SEQ;
    int n = row % NN;
    float x0 = inp[(size_t)row*2 + 0];
    float x1 = inp[(size_t)row*2 + 1];
    float v = fmaf(x0, w_in[t], fmaf(x1, w_in[HID+t], b_in[t]));
    hin[(((size_t)s*B + b)*NN + n)*HID + t] = v;
    if (s == 0) y[((size_t)b*NN + n)*HID + t] = v;
}

// ---------------- W^T fp16 hi/lo split: g_wh/g_wl[n*64 + kword] ----------------
__global__ void k_wsplit(const float* __restrict__ w, unsigned* wh, unsigned* wl){
    int i = blockIdx.x*256 + threadIdx.x;
    if (i >= HID*HID/2) return;
    int n = i >> 6, kw = i & 63;
    int k0 = kw*2;
    float w0 = w[(size_t)k0*HID + n];
    float w1 = w[(size_t)(k0+1)*HID + n];
    wh[i] = packh2(w0, w1);
    wl[i] = packh2(h_res(w0), h_res(w1));
}

// ---------------- CSR construction (deterministic) ----------------
__global__ void k_csr_count(const int* __restrict__ dst, int* cnt){
    int e = blockIdx.x*blockDim.x + threadIdx.x;
    if (e < E) atomicAdd(&cnt[dst[e]], 1);
}
__global__ void k_csr_scan(const int* __restrict__ cnt, int* off){
    __shared__ int s[1024];
    int t = threadIdx.x;
    s[t] = (t < NN) ? cnt[t] : 0;
    __syncthreads();
    #pragma unroll
    for (int o = 1; o < 1024; o <<= 1){
        int v = (t >= o) ? s[t-o] : 0;
        __syncthreads();
        s[t] += v;
        __syncthreads();
    }
    if (t == 0) off[0] = 0;
    if (t < NN) off[t+1] = s[t];
}
__global__ void k_csr_fill(const int* __restrict__ dst, const int* __restrict__ off,
                           int* cur, int* eidx){
    int e = blockIdx.x*blockDim.x + threadIdx.x;
    if (e < E){
        int d = dst[e];
        int p = atomicAdd(&cur[d], 1);
        eidx[off[d] + p] = e;
    }
}
__global__ void k_csr_sort(const int* __restrict__ off, int* eidx){
    if (threadIdx.x != 0) return;
    int n = blockIdx.x;
    int a = off[n], b = off[n+1];
    for (int i = a+1; i < b; i++){
        int v = eidx[i]; int j = i-1;
        while (j >= a && eidx[j] > v){ eidx[j+1] = eidx[j]; j--; }
        eidx[j+1] = v;
    }
}
__global__ void k_csr_gather(const int* __restrict__ eidx, const int* __restrict__ src,
                             int* __restrict__ srcs){
    int i = blockIdx.x*blockDim.x + threadIdx.x;
    if (i < E) srcs[i] = src[eidx[i]];
}

// ========== fp16 HMMA GEMM (GAT path): hp(fp16) = (A0 + c1*A1) @ W_gat ==========
// 64x128 tile, grid 125, 512 threads = 16 warps, each 16x32 out via m16n8k16.
// 3-term split staged in smem; mainloop pure LDS+HMMA. el/er epilogue (R11-verified
// C fragment layout: c0,c1 at (r, 2t, 2t+1); c2,c3 at (r+8, ...)).
__global__ void __launch_bounds__(512) k_gemm_h(
    const float* __restrict__ A0, const float* __restrict__ A1, float c1,
    const unsigned* __restrict__ WH, const unsigned* __restrict__ WL,
    __half* __restrict__ Ch,
    float* __restrict__ el, float* __restrict__ er,
    const float* __restrict__ a_l, const float* __restrict__ a_r)
{
    extern __shared__ unsigned hsm[];
    unsigned* sAh = hsm + A_H_OFF;   // [64][HS]
    unsigned* sAl = hsm + A_L_OFF;
    unsigned* sBh = hsm + B_H_OFF;   // [128][HS]
    unsigned* sBl = hsm + B_L_OFF;

    int tid  = threadIdx.x;
    int lane = tid & 31, w = tid >> 5;
    int row0 = blockIdx.x * 64;
    int mrow = (w & 3) * 16;
    int ncol = (w >> 2) * 32;
    int g = lane >> 2;        // 0..7
    int t = lane & 3;         // 0..3

    // ---- stage B hi/lo (copy, row-padded) ----
    {
        const uint4* H4 = (const uint4*)WH;
        const uint4* L4 = (const uint4*)WL;
        #pragma unroll
        for (int i = tid; i < 2048; i += 512){
            int n = i >> 4, kw = (i & 15) * 4;
            *reinterpret_cast<uint4*>(&sBh[n*HS + kw]) = H4[i];
            *reinterpret_cast<uint4*>(&sBl[n*HS + kw]) = L4[i];
        }
    }
    // ---- stage A hi/lo (fused axpy + fp16 split) ----
    {
        const float4* A04 = (const float4*)A0;
        const float4* A14 = (const float4*)A1;
        #pragma unroll
        for (int i = tid; i < 64*32; i += 512){
            int r = i >> 5, c4 = i & 31;
            float4 v = A04[(size_t)(row0+r)*32 + c4];
            if (A1){
                float4 u = A14[(size_t)(row0+r)*32 + c4];
                v.x = fmaf(c1,u.x,v.x); v.y = fmaf(c1,u.y,v.y);
                v.z = fmaf(c1,u.z,v.z); v.w = fmaf(c1,u.w,v.w);
            }
            int kw = c4*2;
            sAh[r*HS + kw]     = packh2(v.x, v.y);
            sAh[r*HS + kw + 1] = packh2(v.z, v.w);
            sAl[r*HS + kw]     = packh2(h_res(v.x), h_res(v.y));
            sAl[r*HS + kw + 1] = packh2(h_res(v.z), h_res(v.w));
        }
    }
    __syncthreads();

    float acc[4][4];
    #pragma unroll
    for (int i=0;i<4;i++)
        #pragma unroll
        for (int j=0;j<4;j++) acc[i][j] = 0.f;

    const unsigned* pAh1 = sAh + (mrow + g)*HS;
    const unsigned* pAh2 = pAh1 + 8*HS;
    const unsigned* pAl1 = sAl + (mrow + g)*HS;
    const unsigned* pAl2 = pAl1 + 8*HS;

    #pragma unroll
    for (int ks = 0; ks < 8; ks++){
        int kw = ks*8 + t;
        unsigned ah0 = pAh1[kw], ah1 = pAh2[kw], ah2 = pAh1[kw+4], ah3 = pAh2[kw+4];
        unsigned al0 = pAl1[kw], al1 = pAl2[kw], al2 = pAl1[kw+4], al3 = pAl2[kw+4];
        #pragma unroll
        for (int nt = 0; nt < 4; nt++){
            int bi = (ncol + nt*8 + g)*HS + kw;
            unsigned bh0 = sBh[bi], bh1 = sBh[bi+4];
            unsigned bl0 = sBl[bi], bl1 = sBl[bi+4];
            HMMA16(acc[nt], ah0,ah1,ah2,ah3, bh0,bh1);
            HMMA16(acc[nt], al0,al1,al2,al3, bh0,bh1);
            HMMA16(acc[nt], ah0,ah1,ah2,ah3, bl0,bl1);
        }
    }

    // ---- store hp (fp16) ----
    {
        size_t r1 = row0 + mrow + g;
        #pragma unroll
        for (int nt=0; nt<4; nt++){
            int col = ncol + nt*8 + t*2;
            __half2 p0 = __floats2half2_rn(acc[nt][0], acc[nt][1]);
            __half2 p1 = __floats2half2_rn(acc[nt][2], acc[nt][3]);
            *reinterpret_cast<__half2*>(Ch + r1*HID + col)     = p0;
            *reinterpret_cast<__half2*>(Ch + (r1+8)*HID + col) = p1;
        }
    }
    // ---- el/er epilogue (R11-verified layout): warp owns heads h0, h0+1 ----
    {
        int h0 = ncol >> 4;
        float pl[2][2] = {{0.f,0.f},{0.f,0.f}};
        float pr[2][2] = {{0.f,0.f},{0.f,0.f}};
        #pragma unroll
        for (int nt=0; nt<4; nt++){
            int hp_ = nt >> 1;
            int d   = (nt & 1)*8 + t*2;
            int h   = h0 + hp_;
            float l0 = a_l[h*DH + d],  l1 = a_l[h*DH + d + 1];
            float r0 = a_r[h*DH + d],  r1 = a_r[h*DH + d + 1];
            pl[hp_][0] += acc[nt][0]*l0 + acc[nt][1]*l1;
            pl[hp_][1] += acc[nt][2]*l0 + acc[nt][3]*l1;
            pr[hp_][0] += acc[nt][0]*r0 + acc[nt][1]*r1;
            pr[hp_][1] += acc[nt][2]*r0 + acc[nt][3]*r1;
        }
        #pragma unroll
        for (int hp_=0; hp_<2; hp_++){
            #pragma unroll
            for (int rh=0; rh<2; rh++){
                pl[hp_][rh] += __shfl_xor_sync(0xffffffffu, pl[hp_][rh], 1);
                pl[hp_][rh] += __shfl_xor_sync(0xffffffffu, pl[hp_][rh], 2);
                pr[hp_][rh] += __shfl_xor_sync(0xffffffffu, pr[hp_][rh], 1);
                pr[hp_][rh] += __shfl_xor_sync(0xffffffffu, pr[hp_][rh], 2);
            }
        }
        if (t == 0){
            int r1 = row0 + mrow + g;
            el[(size_t)r1*HEADS + h0]       = pl[0][0];
            el[(size_t)(r1+8)*HEADS + h0]   = pl[0][1];
            el[(size_t)r1*HEADS + h0+1]     = pl[1][0];
            el[(size_t)(r1+8)*HEADS + h0+1] = pl[1][1];
            er[(size_t)r1*HEADS + h0]       = pr[0][0];
            er[(size_t)(r1+8)*HEADS + h0]   = pr[0][1];
            er[(size_t)r1*HEADS + h0+1]     = pr[1][0];
            er[(size_t)(r1+8)*HEADS + h0+1] = pr[1][1];
        }
    }
}

// ---------------- FFMA GEMM (tanh/LN + head path; proven) ----------------
__global__ void __launch_bounds__(512) k_gemm(
    const float* __restrict__ A0,
    const float* __restrict__ W0,
    const float* __restrict__ A2, const float* __restrict__ W1,
    const float* __restrict__ b0, const float* __restrict__ b1,
    float* __restrict__ C, int act, int doLN)
{
    extern __shared__ float fsm[];
    float* sW  = fsm;
    float* sAT = fsm + HID*HID;

    int row0 = blockIdx.x * 64;
    int tid = threadIdx.x;
    int tx = tid & 31, ty = tid >> 5;
    int col0 = tx * 4;

    float acc[4][4];
    #pragma unroll
    for (int i=0;i<4;i++)
        #pragma unroll
        for (int j=0;j<4;j++) acc[i][j] = 0.f;

    {
        const float4* W4 = (const float4*)W0;
        float4* sW4 = (float4*)sW;
        #pragma unroll
        for (int i = tid; i < HID*32; i += 512) sW4[i] = W4[i];
        const float4* A04 = (const float4*)A0;
        #pragma unroll
        for (int i = tid; i < 64*32; i += 512){
            int r = i >> 5, c4 = i & 31;
            float4 v = A04[(size_t)(row0+r)*32 + c4];
            int k0 = c4*4;
            sAT[(k0+0)*AT_STRIDE + r] = v.x;
            sAT[(k0+1)*AT_STRIDE + r] = v.y;
            sAT[(k0+2)*AT_STRIDE + r] = v.z;
            sAT[(k0+3)*AT_STRIDE + r] = v.w;
        }
    }
    __syncthreads();
    {
        const float4* sW4 = (const float4*)sW;
        float4 w = sW4[tx];
        float4 a = *reinterpret_cast<const float4*>(sAT + ty*4);
        #pragma unroll 4
        for (int k = 0; k < HID; k++){
            int kn = (k+1) & 127;
            float4 wn = sW4[kn*32 + tx];
            float4 an = *reinterpret_cast<const float4*>(sAT + kn*AT_STRIDE + ty*4);
            acc[0][0]=fmaf(a.x,w.x,acc[0][0]); acc[0][1]=fmaf(a.x,w.y,acc[0][1]);
            acc[0][2]=fmaf(a.x,w.z,acc[0][2]); acc[0][3]=fmaf(a.x,w.w,acc[0][3]);
            acc[1][0]=fmaf(a.y,w.x,acc[1][0]); acc[1][1]=fmaf(a.y,w.y,acc[1][1]);
            acc[1][2]=fmaf(a.y,w.z,acc[1][2]); acc[1][3]=fmaf(a.y,w.w,acc[1][3]);
            acc[2][0]=fmaf(a.z,w.x,acc[2][0]); acc[2][1]=fmaf(a.z,w.y,acc[2][1]);
            acc[2][2]=fmaf(a.z,w.z,acc[2][2]); acc[2][3]=fmaf(a.z,w.w,acc[2][3]);
            acc[3][0]=fmaf(a.w,w.x,acc[3][0]); acc[3][1]=fmaf(a.w,w.y,acc[3][1]);
            acc[3][2]=fmaf(a.w,w.z,acc[3][2]); acc[3][3]=fmaf(a.w,w.w,acc[3][3]);
            w = wn; a = an;
        }
    }
    if (A2){
        __syncthreads();
        {
            const float4* W4 = (const float4*)W1;
            float4* sW4 = (float4*)sW;
            #pragma unroll
            for (int i = tid; i < HID*32; i += 512) sW4[i] = W4[i];
            const float4* A24 = (const float4*)A2;
            #pragma unroll
            for (int i = tid; i < 64*32; i += 512){
                int r = i >> 5, c4 = i & 31;
                float4 v = A24[(size_t)(row0+r)*32 + c4];
                int k0 = c4*4;
                sAT[(k0+0)*AT_STRIDE + r] = v.x;
                sAT[(k0+1)*AT_STRIDE + r] = v.y;
                sAT[(k0+2)*AT_STRIDE + r] = v.z;
                sAT[(k0+3)*AT_STRIDE + r] = v.w;
            }
        }
        __syncthreads();
        const float4* sW4 = (const float4*)sW;
        float4 w = sW4[tx];
        float4 a = *reinterpret_cast<const float4*>(sAT + ty*4);
        #pragma unroll 4
        for (int k = 0; k < HID; k++){
            int kn = (k+1) & 127;
            float4 wn = sW4[kn*32 + tx];
            float4 an = *reinterpret_cast<const float4*>(sAT + kn*AT_STRIDE + ty*4);
            acc[0][0]=fmaf(a.x,w.x,acc[0][0]); acc[0][1]=fmaf(a.x,w.y,acc[0][1]);
            acc[0][2]=fmaf(a.x,w.z,acc[0][2]); acc[0][3]=fmaf(a.x,w.w,acc[0][3]);
            acc[1][0]=fmaf(a.y,w.x,acc[1][0]); acc[1][1]=fmaf(a.y,w.y,acc[1][1]);
            acc[1][2]=fmaf(a.y,w.z,acc[1][2]); acc[1][3]=fmaf(a.y,w.w,acc[1][3]);
            acc[2][0]=fmaf(a.z,w.x,acc[2][0]); acc[2][1]=fmaf(a.z,w.y,acc[2][1]);
            acc[2][2]=fmaf(a.z,w.z,acc[2][2]); acc[2][3]=fmaf(a.z,w.w,acc[2][3]);
            acc[3][0]=fmaf(a.w,w.x,acc[3][0]); acc[3][1]=fmaf(a.w,w.y,acc[3][1]);
            acc[3][2]=fmaf(a.w,w.z,acc[3][2]); acc[3][3]=fmaf(a.w,w.w,acc[3][3]);
            w = wn; a = an;
        }
    }
    float bias[4] = {0.f,0.f,0.f,0.f};
    if (b0){
        #pragma unroll
        for (int j=0;j<4;j++) bias[j] += b0[col0+j];
    }
    if (b1){
        #pragma unroll
        for (int j=0;j<4;j++) bias[j] += b1[col0+j];
    }
    #pragma unroll
    for (int i=0;i<4;i++){
        #pragma unroll
        for (int j=0;j<4;j++){
            acc[i][j] += bias[j];
            if (act) acc[i][j] = tanhf(acc[i][j]);
        }
    }
    if (doLN){
        #pragma unroll
        for (int i=0;i<4;i++){
            float s = acc[i][0]+acc[i][1]+acc[i][2]+acc[i][3];
            #pragma unroll
            for (int o = 16; o > 0; o >>= 1) s += __shfl_xor_sync(0xffffffffu, s, o);
            float mean = s * (1.f/HID);
            float d0 = acc[i][0]-mean, d1 = acc[i][1]-mean,
                  d2 = acc[i][2]-mean, d3 = acc[i][3]-mean;
            float q = d0*d0 + d1*d1 + d2*d2 + d3*d3;
            #pragma unroll
            for (int o = 16; o > 0; o >>= 1) q += __shfl_xor_sync(0xffffffffu, q, o);
            float inv = 1.0f / sqrtf(q * (1.f/HID) + 1e-5f);
            acc[i][0] = d0*inv; acc[i][1] = d1*inv;
            acc[i][2] = d2*inv; acc[i][3] = d3*inv;
        }
    }
    #pragma unroll
    for (int i=0;i<4;i++){
        int r = row0 + ty*4 + i;
        float4 o;
        o.x = acc[i][0]; o.y = acc[i][1]; o.z = acc[i][2]; o.w = acc[i][3];
        *reinterpret_cast<float4*>(C + (size_t)r*HID + col0) = o;
    }
}

// ---------------- GAT: warp-per-(node,batch); fp16 feature gather ----------------
__global__ void __launch_bounds__(256) k_gat(
    const __half* __restrict__ hp, const float* __restrict__ el,
    const float* __restrict__ er,
    const int* __restrict__ off, const int* __restrict__ srcs,
    float* __restrict__ kout,
    const float* __restrict__ yin, const float* __restrict__ k1,
    const float* __restrict__ k2, const float* __restrict__ k3, float dtc)
{
    const unsigned FULL = 0xffffffffu;
    int n    = blockIdx.x;
    int b    = threadIdx.x >> 5;
    int lane = threadIdx.x & 31;
    int bn   = b*NN + n;

    const __half* hb  = hp + (size_t)b*NN*HID;
    const float*  elb = el + (size_t)b*NN*HEADS;

    float erv[8];
    {
        float4 e0v = *reinterpret_cast<const float4*>(er + (size_t)bn*HEADS);
        float4 e1v = *reinterpret_cast<const float4*>(er + (size_t)bn*HEADS + 4);
        erv[0]=e0v.x; erv[1]=e0v.y; erv[2]=e0v.z; erv[3]=e0v.w;
        erv[4]=e1v.x; erv[5]=e1v.y; erv[6]=e1v.z; erv[7]=e1v.w;
    }

    int e0 = off[n], deg = off[n+1] - e0;

    float acc[4] = {0.f,0.f,0.f,0.f};
    float m[8], ssum[8];
    #pragma unroll
    for (int h=0;h<8;h++){ m[h] = -FLT_MAX; ssum[h] = 0.f; }

    for (int base = 0; base < deg; base += 32){
        int cnt = min(32, deg - base);
        int sj = 0;
        float lg[8];
        if (lane < cnt){
            sj = srcs[e0 + base + lane];
            float4 v0 = *reinterpret_cast<const float4*>(elb + (size_t)sj*HEADS);
            float4 v1 = *reinterpret_cast<const float4*>(elb + (size_t)sj*HEADS + 4);
            float t0;
            t0 = v0.x + erv[0]; lg[0] = (t0>=0.f)?t0:0.2f*t0;
            t0 = v0.y + erv[1]; lg[1] = (t0>=0.f)?t0:0.2f*t0;
            t0 = v0.z + erv[2]; lg[2] = (t0>=0.f)?t0:0.2f*t0;
            t0 = v0.w + erv[3]; lg[3] = (t0>=0.f)?t0:0.2f*t0;
            t0 = v1.x + erv[4]; lg[4] = (t0>=0.f)?t0:0.2f*t0;
            t0 = v1.y + erv[5]; lg[5] = (t0>=0.f)?t0:0.2f*t0;
            t0 = v1.z + erv[6]; lg[6] = (t0>=0.f)?t0:0.2f*t0;
            t0 = v1.w + erv[7]; lg[7] = (t0>=0.f)?t0:0.2f*t0;
        } else {
            #pragma unroll
            for (int h=0;h<8;h++) lg[h] = -FLT_MAX;
        }
        float nm[8];
        #pragma unroll
        for (int h=0;h<8;h++) nm[h] = lg[h];
        #pragma unroll
        for (int o = 16; o > 0; o >>= 1){
            #pragma unroll
            for (int h=0;h<8;h++)
                nm[h] = fmaxf(nm[h], __shfl_xor_sync(FULL, nm[h], o));
        }
        float w[8], sc[8];
        #pragma unroll
        for (int h=0;h<8;h++){
            float newm = fmaxf(m[h], nm[h]);
            sc[h] = (m[h] == -FLT_MAX) ? 0.f : __expf(m[h] - newm);
            m[h]  = newm;
            w[h]  = __expf(lg[h] - newm);
        }
        if (base > 0){
            #pragma unroll
            for (int g=0;g<4;g++){
                float s01 = (lane < 16) ? sc[2*g] : sc[2*g+1];
                acc[g] *= s01;
            }
            #pragma unroll
            for (int h=0;h<8;h++) ssum[h] *= sc[h];
        }
        float cs[8];
        #pragma unroll
        for (int h=0;h<8;h++) cs[h] = w[h];
        #pragma unroll
        for (int o = 16; o > 0; o >>= 1){
            #pragma unroll
            for (int h=0;h<8;h++)
                cs[h] += __shfl_xor_sync(FULL, cs[h], o);
        }
        #pragma unroll
        for (int h=0;h<8;h++) ssum[h] += cs[h];
        for (int j = 0; j < cnt; j++){
            int s = __shfl_sync(FULL, sj, j);
            const __half* hr = hb + (size_t)s*HID;
            float h0 = __half2float(hr[lane]);
            float h1 = __half2float(hr[lane + 32]);
            float h2 = __half2float(hr[lane + 64]);
            float h3 = __half2float(hr[lane + 96]);
            float w0 = __shfl_sync(FULL, w[0], j);
            float w1 = __shfl_sync(FULL, w[1], j);
            float w2 = __shfl_sync(FULL, w[2], j);
            float w3 = __shfl_sync(FULL, w[3], j);
            float w4 = __shfl_sync(FULL, w[4], j);
            float w5 = __shfl_sync(FULL, w[5], j);
            float w6 = __shfl_sync(FULL, w[6], j);
            float w7 = __shfl_sync(FULL, w[7], j);
            bool lo = (lane < 16);
            acc[0] = fmaf(lo ? w0 : w1, h0, acc[0]);
            acc[1] = fmaf(lo ? w2 : w3, h1, acc[1]);
            acc[2] = fmaf(lo ? w4 : w5, h2, acc[2]);
            acc[3] = fmaf(lo ? w6 : w7, h3, acc[3]);
        }
    }
    #pragma unroll
    for (int g=0;g<4;g++){
        float s = ((lane < 16) ? ssum[2*g] : ssum[2*g+1]) + 1e-16f;
        float kv = acc[g] / s;
        size_t o = (size_t)bn*HID + lane + 32*g;
        if (yin){
            kout[o] = yin[o] + dtc*(k1[o] + 2.f*k2[o] + 2.f*k3[o] + kv);
        } else {
            kout[o] = kv;
        }
    }
}

// ---------------- LayerNorm (idx==0 only) ----------------
__global__ void __launch_bounds__(128) k_ln(const float* __restrict__ s, float* __restrict__ d){
    int row = blockIdx.x;
    int t = threadIdx.x;
    __shared__ float sh[4];
    float v = s[(size_t)row*HID + t];

    float a = v;
    #pragma unroll
    for (int o = 16; o > 0; o >>= 1) a += __shfl_xor_sync(0xffffffffu, a, o);
    if ((t & 31) == 0) sh[t >> 5] = a;
    __syncthreads();
    float mean = (sh[0]+sh[1]+sh[2]+sh[3]) * (1.f/HID);

    float dv = v - mean;
    float q = dv*dv;
    __syncthreads();
    #pragma unroll
    for (int o = 16; o > 0; o >>= 1) q += __shfl_xor_sync(0xffffffffu, q, o);
    if ((t & 31) == 0) sh[t >> 5] = q;
    __syncthreads();
    float var = (sh[0]+sh[1]+sh[2]+sh[3]) * (1.f/HID);

    d[(size_t)row*HID + t] = dv / sqrtf(var + 1e-5f);
}

// ---------------- launch ----------------
extern "C" void kernel_launch(void* const* d_in, const int* in_sizes, int n_in,
                              void* d_out, int out_size)
{
    const float* inputs = (const float*)d_in[0];
    const int*   src    = (const int*)  d_in[1];
    const int*   dst    = (const int*)  d_in[2];
    const float* w_in   = (const float*)d_in[3];
    const float* b_in   = (const float*)d_in[4];
    const float* w_gat  = (const float*)d_in[5];
    const float* a_l    = (const float*)d_in[6];
    const float* a_r    = (const float*)d_in[7];
    const float* w_W    = (const float*)d_in[8];
    const float* b_W    = (const float*)d_in[9];
    const float* w_U    = (const float*)d_in[10];
    const float* b_U    = (const float*)d_in[11];
    const float* w_o1   = (const float*)d_in[12];
    const float* b_o1   = (const float*)d_in[13];
    const float* w_o2   = (const float*)d_in[14];
    const float* b_o2   = (const float*)d_in[15];
    float* out = (float*)d_out;

    float *hin, *y, *k1, *k2, *k3, *tmp, *el, *er;
    __half *hp;
    unsigned *wh, *wl;
    int *cnt, *cur, *off, *eidx, *srcs;
    cudaGetSymbolAddress((void**)&hin, g_hin);
    cudaGetSymbolAddress((void**)&y,   g_y);
    cudaGetSymbolAddress((void**)&hp,  g_hp);
    cudaGetSymbolAddress((void**)&k1,  g_k1);
    cudaGetSymbolAddress((void**)&k2,  g_k2);
    cudaGetSymbolAddress((void**)&k3,  g_k3);
    cudaGetSymbolAddress((void**)&tmp, g_tmp);
    cudaGetSymbolAddress((void**)&el,  g_el);
    cudaGetSymbolAddress((void**)&er,  g_er);
    cudaGetSymbolAddress((void**)&wh,  g_wh);
    cudaGetSymbolAddress((void**)&wl,  g_wl);
    cudaGetSymbolAddress((void**)&cnt, g_cnt);
    cudaGetSymbolAddress((void**)&cur, g_cur);
    cudaGetSymbolAddress((void**)&off, g_off);
    cudaGetSymbolAddress((void**)&eidx,g_eidx);
    cudaGetSymbolAddress((void**)&srcs,g_srcs);

    const float* F0 = (const float*)0;

    static bool attr_set = false;
    if (!attr_set){
        cudaFuncSetAttribute(k_gemm,   cudaFuncAttributeMaxDynamicSharedMemorySize, GEMM_SMEM);
        cudaFuncSetAttribute(k_gemm_h, cudaFuncAttributeMaxDynamicSharedMemorySize, HMMA_SMEM);
        attr_set = true;
    }

    const float dt  = 0.25f;
    const float dtc = dt / 6.0f;

    // prelude
    k_init      <<<B*SEQ*NN, HID>>>(inputs, w_in, b_in, hin, y, cnt, cur);
    k_wsplit    <<<(HID*HID/2+255)/256, 256>>>(w_gat, wh, wl);
    k_csr_count <<<(E+255)/256, 256>>>(dst, cnt);
    k_csr_scan  <<<1, 1024>>>(cnt, off);

    // first RK4 stage-1 GEMM (does not need CSR) — ncu -s 5 capture slot
    k_gemm_h<<<125,512,HMMA_SMEM>>>(y, F0, 0.f, wh, wl, hp, el, er, a_l, a_r);

    k_csr_fill  <<<(E+255)/256, 256>>>(dst, off, cur, eidx);
    k_csr_sort  <<<NN, 32>>>(off, eidx);
    k_csr_gather<<<(E+255)/256, 256>>>(eidx, src, srcs);

    for (int idx = 0; idx < SEQ; idx++){
        for (int s = 0; s < 4; s++){
            if (!(idx == 0 && s == 0)){
                k_gemm_h<<<125,512,HMMA_SMEM>>>(y, F0, 0.f, wh, wl, hp, el, er, a_l, a_r);
            }
            k_gat <<<NN,256>>>(hp, el, er, off, srcs, k1, F0,F0,F0,F0, 0.f);
            k_gemm_h<<<125,512,HMMA_SMEM>>>(y, k1, 0.5f*dt, wh, wl, hp, el, er, a_l, a_r);
            k_gat <<<NN,256>>>(hp, el, er, off, srcs, k2, F0,F0,F0,F0, 0.f);
            k_gemm_h<<<125,512,HMMA_SMEM>>>(y, k2, 0.5f*dt, wh, wl, hp, el, er, a_l, a_r);
            k_gat <<<NN,256>>>(hp, el, er, off, srcs, k3, F0,F0,F0,F0, 0.f);
            k_gemm_h<<<125,512,HMMA_SMEM>>>(y, k3, dt, wh, wl, hp, el, er, a_l, a_r);
            k_gat <<<NN,256>>>(hp, el, er, off, srcs, y, y, k1, k2, k3, dtc);
        }
        if (idx > 0){
            // y = LN(tanh(y@w_W + h[idx]@w_U + b_W + b_U)) — LN fused (FFMA path)
            const float* hidx = hin + (size_t)idx * M_ROWS * HID;
            k_gemm<<<125,512,GEMM_SMEM>>>(y, w_W, hidx, w_U, b_W, b_U, y, 1, 1);
        } else {
            k_ln  <<<M_ROWS,128>>>(y, y);
        }
    }

    // out = tanh(y@w_o1 + b_o1) @ w_o2 + b_o2  (FFMA path)
    k_gemm<<<125,512,GEMM_SMEM>>>(y,   w_o1, F0, F0, b_o1, F0, tmp, 1, 0);
    k_gemm<<<125,512,GEMM_SMEM>>>(tmp, w_o2, F0, F0, b_o2, F0, out, 0, 0);
}

// round 15
// speedup vs baseline: 1.4439x; 1.1008x over previous
#include <cuda_runtime.h>
#include <cuda_fp16.h>
#include <math.h>
#include <float.h>
#include <stdint.h>

#define B 8
#define SEQ 12
#define NN 1000
#define E 16000
#define HID 128
#define HEADS 8
#define DH 16
#define M_ROWS (B*NN)          /* 8000 */

#define AT_STRIDE 68
#define GEMM_SMEM (HID*HID*4 + HID*AT_STRIDE*4)   /* FFMA gemm */

/* fp16-mma gemm smem (uint32 words), stride 68 words per row */
#define HS 68
#define A_H_OFF 0
#define A_L_OFF (64*HS)
#define B_H_OFF (2*64*HS)
#define HMMA_SMEM ((2*64*HS + 128*HS)*4)   /* 69632 B */

// ---------------- static device scratch ----------------
__device__ float    g_hin[(size_t)SEQ*B*NN*HID];
__device__ float    g_y  [(size_t)M_ROWS*HID];
__device__ __half   g_hp [(size_t)M_ROWS*HID];
__device__ float    g_k1 [(size_t)M_ROWS*HID];
__device__ float    g_k2 [(size_t)M_ROWS*HID];
__device__ float    g_k3 [(size_t)M_ROWS*HID];
__device__ float    g_tmp[(size_t)M_ROWS*HID];
__device__ float    g_el [(size_t)M_ROWS*HEADS];
__device__ float    g_er [(size_t)M_ROWS*HEADS];
__device__ unsigned g_wh [HID*HID/2];   /* W^T fp16 hi: [n][kword] */
__device__ int      g_cnt[NN];
__device__ int      g_cur[NN];
__device__ int      g_off[NN+1];
__device__ int      g_eidx[E];
__device__ int      g_srcs[E];

// ---------------- helpers ----------------
__device__ __forceinline__ unsigned packh2(float a, float b){
    __half2 t = __floats2half2_rn(a, b);
    unsigned u; memcpy(&u, &t, 4); return u;
}
__device__ __forceinline__ float h_res(float x){
    return x - __half2float(__float2half_rn(x));
}
#define HMMA16(c, a0,a1,a2,a3, b0,b1) \
    asm volatile("mma.sync.aligned.m16n8k16.row.col.f32.f16.f16.f32 " \
        "{%0,%1,%2,%3}, {%4,%5,%6,%7}, {%8,%9}, {%0,%1,%2,%3};" \
        : "+f"((c)[0]), "+f"((c)[1]), "+f"((c)[2]), "+f"((c)[3]) \
        : "r"(a0), "r"(a1), "r"(a2), "r"(a3), "r"(b0), "r"(b1))

// ---------------- fused init: inproj + y=h[:,0] + CSR zero ----------------
__global__ void k_init(const float* __restrict__ inp, const float* __restrict__ w_in,
                       const float* __restrict__ b_in, float* __restrict__ hin,
                       float* __restrict__ y, int* cnt, int* cur){
    int row = blockIdx.x;
    int t = threadIdx.x;
    if (blockIdx.x < 8){
        int q = blockIdx.x*128 + t;
        if (q < NN){ cnt[q] = 0; cur[q] = 0; }
    }
    int b = row / (SEQ*NN);
    int s = (row / NN) % SEQ;
    int n = row % NN;
    float x0 = inp[(size_t)row*2 + 0];
    float x1 = inp[(size_t)row*2 + 1];
    float v = fmaf(x0, w_in[t], fmaf(x1, w_in[HID+t], b_in[t]));
    hin[(((size_t)s*B + b)*NN + n)*HID + t] = v;
    if (s == 0) y[((size_t)b*NN + n)*HID + t] = v;
}

// ---------------- W^T fp16 split: g_wh[n*64 + kword] ----------------
__global__ void k_wsplit(const float* __restrict__ w, unsigned* wh){
    int i = blockIdx.x*256 + threadIdx.x;
    if (i >= HID*HID/2) return;
    int n = i >> 6, kw = i & 63;
    int k0 = kw*2;
    wh[i] = packh2(w[(size_t)k0*HID + n], w[(size_t)(k0+1)*HID + n]);
}

// ---------------- CSR construction (deterministic) ----------------
__global__ void k_csr_count(const int* __restrict__ dst, int* cnt){
    int e = blockIdx.x*blockDim.x + threadIdx.x;
    if (e < E) atomicAdd(&cnt[dst[e]], 1);
}
__global__ void k_csr_scan(const int* __restrict__ cnt, int* off){
    __shared__ int s[1024];
    int t = threadIdx.x;
    s[t] = (t < NN) ? cnt[t] : 0;
    __syncthreads();
    #pragma unroll
    for (int o = 1; o < 1024; o <<= 1){
        int v = (t >= o) ? s[t-o] : 0;
        __syncthreads();
        s[t] += v;
        __syncthreads();
    }
    if (t == 0) off[0] = 0;
    if (t < NN) off[t+1] = s[t];
}
__global__ void k_csr_fill(const int* __restrict__ dst, const int* __restrict__ off,
                           int* cur, int* eidx){
    int e = blockIdx.x*blockDim.x + threadIdx.x;
    if (e < E){
        int d = dst[e];
        int p = atomicAdd(&cur[d], 1);
        eidx[off[d] + p] = e;
    }
}
__global__ void k_csr_sort(const int* __restrict__ off, int* eidx){
    if (threadIdx.x != 0) return;
    int n = blockIdx.x;
    int a = off[n], b = off[n+1];
    for (int i = a+1; i < b; i++){
        int v = eidx[i]; int j = i-1;
        while (j >= a && eidx[j] > v){ eidx[j+1] = eidx[j]; j--; }
        eidx[j+1] = v;
    }
}
__global__ void k_csr_gather(const int* __restrict__ eidx, const int* __restrict__ src,
                             int* __restrict__ srcs){
    int i = blockIdx.x*blockDim.x + threadIdx.x;
    if (i < E) srcs[i] = src[eidx[i]];
}

// ========== fp16 HMMA GEMM (GAT path): hp(fp16) = (A0 + c1*A1) @ W_gat ==========
// 2-term split: Ah*Wh + Al*Wh (W effectively fp16). 64x128 tile, grid 125,
// 512 threads = 16 warps, 16x32 out each via m16n8k16.
__global__ void __launch_bounds__(512) k_gemm_h(
    const float* __restrict__ A0, const float* __restrict__ A1, float c1,
    const unsigned* __restrict__ WH,
    __half* __restrict__ Ch,
    float* __restrict__ el, float* __restrict__ er,
    const float* __restrict__ a_l, const float* __restrict__ a_r)
{
    extern __shared__ unsigned hsm[];
    unsigned* sAh = hsm + A_H_OFF;   // [64][HS]
    unsigned* sAl = hsm + A_L_OFF;
    unsigned* sBh = hsm + B_H_OFF;   // [128][HS]

    int tid  = threadIdx.x;
    int lane = tid & 31, w = tid >> 5;
    int row0 = blockIdx.x * 64;
    int mrow = (w & 3) * 16;
    int ncol = (w >> 2) * 32;
    int g = lane >> 2;        // 0..7
    int t = lane & 3;         // 0..3

    // ---- stage B hi (copy, row-padded) ----
    {
        const uint4* H4 = (const uint4*)WH;
        #pragma unroll
        for (int i = tid; i < 2048; i += 512){
            int n = i >> 4, kw = (i & 15) * 4;
            *reinterpret_cast<uint4*>(&sBh[n*HS + kw]) = H4[i];
        }
    }
    // ---- stage A hi/lo (fused axpy + fp16 split) ----
    {
        const float4* A04 = (const float4*)A0;
        const float4* A14 = (const float4*)A1;
        #pragma unroll
        for (int i = tid; i < 64*32; i += 512){
            int r = i >> 5, c4 = i & 31;
            float4 v = A04[(size_t)(row0+r)*32 + c4];
            if (A1){
                float4 u = A14[(size_t)(row0+r)*32 + c4];
                v.x = fmaf(c1,u.x,v.x); v.y = fmaf(c1,u.y,v.y);
                v.z = fmaf(c1,u.z,v.z); v.w = fmaf(c1,u.w,v.w);
            }
            int kw = c4*2;
            sAh[r*HS + kw]     = packh2(v.x, v.y);
            sAh[r*HS + kw + 1] = packh2(v.z, v.w);
            sAl[r*HS + kw]     = packh2(h_res(v.x), h_res(v.y));
            sAl[r*HS + kw + 1] = packh2(h_res(v.z), h_res(v.w));
        }
    }
    __syncthreads();

    float acc[4][4];
    #pragma unroll
    for (int i=0;i<4;i++)
        #pragma unroll
        for (int j=0;j<4;j++) acc[i][j] = 0.f;

    const unsigned* pAh1 = sAh + (mrow + g)*HS;
    const unsigned* pAh2 = pAh1 + 8*HS;
    const unsigned* pAl1 = sAl + (mrow + g)*HS;
    const unsigned* pAl2 = pAl1 + 8*HS;

    #pragma unroll
    for (int ks = 0; ks < 8; ks++){
        int kw = ks*8 + t;
        unsigned ah0 = pAh1[kw], ah1 = pAh2[kw], ah2 = pAh1[kw+4], ah3 = pAh2[kw+4];
        unsigned al0 = pAl1[kw], al1 = pAl2[kw], al2 = pAl1[kw+4], al3 = pAl2[kw+4];
        #pragma unroll
        for (int nt = 0; nt < 4; nt++){
            int bi = (ncol + nt*8 + g)*HS + kw;
            unsigned bh0 = sBh[bi], bh1 = sBh[bi+4];
            HMMA16(acc[nt], ah0,ah1,ah2,ah3, bh0,bh1);
            HMMA16(acc[nt], al0,al1,al2,al3, bh0,bh1);
        }
    }

    // ---- store hp (fp16) ----
    {
        size_t r1 = row0 + mrow + g;
        #pragma unroll
        for (int nt=0; nt<4; nt++){
            int col = ncol + nt*8 + t*2;
            __half2 p0 = __floats2half2_rn(acc[nt][0], acc[nt][1]);
            __half2 p1 = __floats2half2_rn(acc[nt][2], acc[nt][3]);
            *reinterpret_cast<__half2*>(Ch + r1*HID + col)     = p0;
            *reinterpret_cast<__half2*>(Ch + (r1+8)*HID + col) = p1;
        }
    }
    // ---- el/er epilogue (verified fragment layout) ----
    {
        int h0 = ncol >> 4;
        float pl[2][2] = {{0.f,0.f},{0.f,0.f}};
        float pr[2][2] = {{0.f,0.f},{0.f,0.f}};
        #pragma unroll
        for (int nt=0; nt<4; nt++){
            int hp_ = nt >> 1;
            int d   = (nt & 1)*8 + t*2;
            int h   = h0 + hp_;
            float l0 = a_l[h*DH + d],  l1 = a_l[h*DH + d + 1];
            float r0 = a_r[h*DH + d],  r1 = a_r[h*DH + d + 1];
            pl[hp_][0] += acc[nt][0]*l0 + acc[nt][1]*l1;
            pl[hp_][1] += acc[nt][2]*l0 + acc[nt][3]*l1;
            pr[hp_][0] += acc[nt][0]*r0 + acc[nt][1]*r1;
            pr[hp_][1] += acc[nt][2]*r0 + acc[nt][3]*r1;
        }
        #pragma unroll
        for (int hp_=0; hp_<2; hp_++){
            #pragma unroll
            for (int rh=0; rh<2; rh++){
                pl[hp_][rh] += __shfl_xor_sync(0xffffffffu, pl[hp_][rh], 1);
                pl[hp_][rh] += __shfl_xor_sync(0xffffffffu, pl[hp_][rh], 2);
                pr[hp_][rh] += __shfl_xor_sync(0xffffffffu, pr[hp_][rh], 1);
                pr[hp_][rh] += __shfl_xor_sync(0xffffffffu, pr[hp_][rh], 2);
            }
        }
        if (t == 0){
            int r1 = row0 + mrow + g;
            el[(size_t)r1*HEADS + h0]       = pl[0][0];
            el[(size_t)(r1+8)*HEADS + h0]   = pl[0][1];
            el[(size_t)r1*HEADS + h0+1]     = pl[1][0];
            el[(size_t)(r1+8)*HEADS + h0+1] = pl[1][1];
            er[(size_t)r1*HEADS + h0]       = pr[0][0];
            er[(size_t)(r1+8)*HEADS + h0]   = pr[0][1];
            er[(size_t)r1*HEADS + h0+1]     = pr[1][0];
            er[(size_t)(r1+8)*HEADS + h0+1] = pr[1][1];
        }
    }
}

// ---------------- FFMA GEMM (tanh/LN + head path; proven) ----------------
__global__ void __launch_bounds__(512) k_gemm(
    const float* __restrict__ A0,
    const float* __restrict__ W0,
    const float* __restrict__ A2, const float* __restrict__ W1,
    const float* __restrict__ b0, const float* __restrict__ b1,
    float* __restrict__ C, int act, int doLN)
{
    extern __shared__ float fsm[];
    float* sW  = fsm;
    float* sAT = fsm + HID*HID;

    int row0 = blockIdx.x * 64;
    int tid = threadIdx.x;
    int tx = tid & 31, ty = tid >> 5;
    int col0 = tx * 4;

    float acc[4][4];
    #pragma unroll
    for (int i=0;i<4;i++)
        #pragma unroll
        for (int j=0;j<4;j++) acc[i][j] = 0.f;

    {
        const float4* W4 = (const float4*)W0;
        float4* sW4 = (float4*)sW;
        #pragma unroll
        for (int i = tid; i < HID*32; i += 512) sW4[i] = W4[i];
        const float4* A04 = (const float4*)A0;
        #pragma unroll
        for (int i = tid; i < 64*32; i += 512){
            int r = i >> 5, c4 = i & 31;
            float4 v = A04[(size_t)(row0+r)*32 + c4];
            int k0 = c4*4;
            sAT[(k0+0)*AT_STRIDE + r] = v.x;
            sAT[(k0+1)*AT_STRIDE + r] = v.y;
            sAT[(k0+2)*AT_STRIDE + r] = v.z;
            sAT[(k0+3)*AT_STRIDE + r] = v.w;
        }
    }
    __syncthreads();
    {
        const float4* sW4 = (const float4*)sW;
        float4 w = sW4[tx];
        float4 a = *reinterpret_cast<const float4*>(sAT + ty*4);
        #pragma unroll 4
        for (int k = 0; k < HID; k++){
            int kn = (k+1) & 127;
            float4 wn = sW4[kn*32 + tx];
            float4 an = *reinterpret_cast<const float4*>(sAT + kn*AT_STRIDE + ty*4);
            acc[0][0]=fmaf(a.x,w.x,acc[0][0]); acc[0][1]=fmaf(a.x,w.y,acc[0][1]);
            acc[0][2]=fmaf(a.x,w.z,acc[0][2]); acc[0][3]=fmaf(a.x,w.w,acc[0][3]);
            acc[1][0]=fmaf(a.y,w.x,acc[1][0]); acc[1][1]=fmaf(a.y,w.y,acc[1][1]);
            acc[1][2]=fmaf(a.y,w.z,acc[1][2]); acc[1][3]=fmaf(a.y,w.w,acc[1][3]);
            acc[2][0]=fmaf(a.z,w.x,acc[2][0]); acc[2][1]=fmaf(a.z,w.y,acc[2][1]);
            acc[2][2]=fmaf(a.z,w.z,acc[2][2]); acc[2][3]=fmaf(a.z,w.w,acc[2][3]);
            acc[3][0]=fmaf(a.w,w.x,acc[3][0]); acc[3][1]=fmaf(a.w,w.y,acc[3][1]);
            acc[3][2]=fmaf(a.w,w.z,acc[3][2]); acc[3][3]=fmaf(a.w,w.w,acc[3][3]);
            w = wn; a = an;
        }
    }
    if (A2){
        __syncthreads();
        {
            const float4* W4 = (const float4*)W1;
            float4* sW4 = (float4*)sW;
            #pragma unroll
            for (int i = tid; i < HID*32; i += 512) sW4[i] = W4[i];
            const float4* A24 = (const float4*)A2;
            #pragma unroll
            for (int i = tid; i < 64*32; i += 512){
                int r = i >> 5, c4 = i & 31;
                float4 v = A24[(size_t)(row0+r)*32 + c4];
                int k0 = c4*4;
                sAT[(k0+0)*AT_STRIDE + r] = v.x;
                sAT[(k0+1)*AT_STRIDE + r] = v.y;
                sAT[(k0+2)*AT_STRIDE + r] = v.z;
                sAT[(k0+3)*AT_STRIDE + r] = v.w;
            }
        }
        __syncthreads();
        const float4* sW4 = (const float4*)sW;
        float4 w = sW4[tx];
        float4 a = *reinterpret_cast<const float4*>(sAT + ty*4);
        #pragma unroll 4
        for (int k = 0; k < HID; k++){
            int kn = (k+1) & 127;
            float4 wn = sW4[kn*32 + tx];
            float4 an = *reinterpret_cast<const float4*>(sAT + kn*AT_STRIDE + ty*4);
            acc[0][0]=fmaf(a.x,w.x,acc[0][0]); acc[0][1]=fmaf(a.x,w.y,acc[0][1]);
            acc[0][2]=fmaf(a.x,w.z,acc[0][2]); acc[0][3]=fmaf(a.x,w.w,acc[0][3]);
            acc[1][0]=fmaf(a.y,w.x,acc[1][0]); acc[1][1]=fmaf(a.y,w.y,acc[1][1]);
            acc[1][2]=fmaf(a.y,w.z,acc[1][2]); acc[1][3]=fmaf(a.y,w.w,acc[1][3]);
            acc[2][0]=fmaf(a.z,w.x,acc[2][0]); acc[2][1]=fmaf(a.z,w.y,acc[2][1]);
            acc[2][2]=fmaf(a.z,w.z,acc[2][2]); acc[2][3]=fmaf(a.z,w.w,acc[2][3]);
            acc[3][0]=fmaf(a.w,w.x,acc[3][0]); acc[3][1]=fmaf(a.w,w.y,acc[3][1]);
            acc[3][2]=fmaf(a.w,w.z,acc[3][2]); acc[3][3]=fmaf(a.w,w.w,acc[3][3]);
            w = wn; a = an;
        }
    }
    float bias[4] = {0.f,0.f,0.f,0.f};
    if (b0){
        #pragma unroll
        for (int j=0;j<4;j++) bias[j] += b0[col0+j];
    }
    if (b1){
        #pragma unroll
        for (int j=0;j<4;j++) bias[j] += b1[col0+j];
    }
    #pragma unroll
    for (int i=0;i<4;i++){
        #pragma unroll
        for (int j=0;j<4;j++){
            acc[i][j] += bias[j];
            if (act) acc[i][j] = tanhf(acc[i][j]);
        }
    }
    if (doLN){
        #pragma unroll
        for (int i=0;i<4;i++){
            float s = acc[i][0]+acc[i][1]+acc[i][2]+acc[i][3];
            #pragma unroll
            for (int o = 16; o > 0; o >>= 1) s += __shfl_xor_sync(0xffffffffu, s, o);
            float mean = s * (1.f/HID);
            float d0 = acc[i][0]-mean, d1 = acc[i][1]-mean,
                  d2 = acc[i][2]-mean, d3 = acc[i][3]-mean;
            float q = d0*d0 + d1*d1 + d2*d2 + d3*d3;
            #pragma unroll
            for (int o = 16; o > 0; o >>= 1) q += __shfl_xor_sync(0xffffffffu, q, o);
            float inv = 1.0f / sqrtf(q * (1.f/HID) + 1e-5f);
            acc[i][0] = d0*inv; acc[i][1] = d1*inv;
            acc[i][2] = d2*inv; acc[i][3] = d3*inv;
        }
    }
    #pragma unroll
    for (int i=0;i<4;i++){
        int r = row0 + ty*4 + i;
        float4 o;
        o.x = acc[i][0]; o.y = acc[i][1]; o.z = acc[i][2]; o.w = acc[i][3];
        *reinterpret_cast<float4*>(C + (size_t)r*HID + col0) = o;
    }
}

// ---------------- GAT: warp-per-(node,batch); smem weight buffer ----------------
__global__ void __launch_bounds__(256) k_gat(
    const __half* __restrict__ hp, const float* __restrict__ el,
    const float* __restrict__ er,
    const int* __restrict__ off, const int* __restrict__ srcs,
    float* __restrict__ kout,
    const float* __restrict__ yin, const float* __restrict__ k1,
    const float* __restrict__ k2, const float* __restrict__ k3, float dtc)
{
    const unsigned FULL = 0xffffffffu;
    __shared__ float s_wbuf[8*32*8];       // [warp][j][head]
    int n    = blockIdx.x;
    int b    = threadIdx.x >> 5;
    int lane = threadIdx.x & 31;
    int bn   = b*NN + n;
    float* swp = s_wbuf + b*(32*8);
    int hi = lane >> 4;                    // 0 or 1: even/odd head of pair

    const __half* hb  = hp + (size_t)b*NN*HID;
    const float*  elb = el + (size_t)b*NN*HEADS;

    float erv[8];
    {
        float4 e0v = *reinterpret_cast<const float4*>(er + (size_t)bn*HEADS);
        float4 e1v = *reinterpret_cast<const float4*>(er + (size_t)bn*HEADS + 4);
        erv[0]=e0v.x; erv[1]=e0v.y; erv[2]=e0v.z; erv[3]=e0v.w;
        erv[4]=e1v.x; erv[5]=e1v.y; erv[6]=e1v.z; erv[7]=e1v.w;
    }

    int e0 = off[n], deg = off[n+1] - e0;

    float acc[4] = {0.f,0.f,0.f,0.f};
    float m[8], ssum[8];
    #pragma unroll
    for (int h=0;h<8;h++){ m[h] = -FLT_MAX; ssum[h] = 0.f; }

    for (int base = 0; base < deg; base += 32){
        int cnt = min(32, deg - base);
        int sj = 0;
        float lg[8];
        if (lane < cnt){
            sj = srcs[e0 + base + lane];
            float4 v0 = *reinterpret_cast<const float4*>(elb + (size_t)sj*HEADS);
            float4 v1 = *reinterpret_cast<const float4*>(elb + (size_t)sj*HEADS + 4);
            float t0;
            t0 = v0.x + erv[0]; lg[0] = (t0>=0.f)?t0:0.2f*t0;
            t0 = v0.y + erv[1]; lg[1] = (t0>=0.f)?t0:0.2f*t0;
            t0 = v0.z + erv[2]; lg[2] = (t0>=0.f)?t0:0.2f*t0;
            t0 = v0.w + erv[3]; lg[3] = (t0>=0.f)?t0:0.2f*t0;
            t0 = v1.x + erv[4]; lg[4] = (t0>=0.f)?t0:0.2f*t0;
            t0 = v1.y + erv[5]; lg[5] = (t0>=0.f)?t0:0.2f*t0;
            t0 = v1.z + erv[6]; lg[6] = (t0>=0.f)?t0:0.2f*t0;
            t0 = v1.w + erv[7]; lg[7] = (t0>=0.f)?t0:0.2f*t0;
        } else {
            #pragma unroll
            for (int h=0;h<8;h++) lg[h] = -FLT_MAX;
        }
        float nm[8];
        #pragma unroll
        for (int h=0;h<8;h++) nm[h] = lg[h];
        #pragma unroll
        for (int o = 16; o > 0; o >>= 1){
            #pragma unroll
            for (int h=0;h<8;h++)
                nm[h] = fmaxf(nm[h], __shfl_xor_sync(FULL, nm[h], o));
        }
        float w[8], sc[8];
        #pragma unroll
        for (int h=0;h<8;h++){
            float newm = fmaxf(m[h], nm[h]);
            sc[h] = (m[h] == -FLT_MAX) ? 0.f : __expf(m[h] - newm);
            m[h]  = newm;
            w[h]  = __expf(lg[h] - newm);
        }
        if (base > 0){
            #pragma unroll
            for (int g=0;g<4;g++){
                float s01 = (lane < 16) ? sc[2*g] : sc[2*g+1];
                acc[g] *= s01;
            }
            #pragma unroll
            for (int h=0;h<8;h++) ssum[h] *= sc[h];
        }
        float cs[8];
        #pragma unroll
        for (int h=0;h<8;h++) cs[h] = w[h];
        #pragma unroll
        for (int o = 16; o > 0; o >>= 1){
            #pragma unroll
            for (int h=0;h<8;h++)
                cs[h] += __shfl_xor_sync(FULL, cs[h], o);
        }
        #pragma unroll
        for (int h=0;h<8;h++) ssum[h] += cs[h];
        // publish chunk weights to smem (per-warp tile), then broadcast-read
        __syncwarp();
        *reinterpret_cast<float4*>(&swp[lane*8])   = make_float4(w[0],w[1],w[2],w[3]);
        *reinterpret_cast<float4*>(&swp[lane*8+4]) = make_float4(w[4],w[5],w[6],w[7]);
        __syncwarp();
        for (int j = 0; j < cnt; j++){
            int s = __shfl_sync(FULL, sj, j);
            const __half* hr = hb + (size_t)s*HID;
            const float*  wj = swp + j*8 + hi;
            float h0 = __half2float(hr[lane]);
            float h1 = __half2float(hr[lane + 32]);
            float h2 = __half2float(hr[lane + 64]);
            float h3 = __half2float(hr[lane + 96]);
            acc[0] = fmaf(wj[0], h0, acc[0]);
            acc[1] = fmaf(wj[2], h1, acc[1]);
            acc[2] = fmaf(wj[4], h2, acc[2]);
            acc[3] = fmaf(wj[6], h3, acc[3]);
        }
    }
    #pragma unroll
    for (int g=0;g<4;g++){
        float s = ((lane < 16) ? ssum[2*g] : ssum[2*g+1]) + 1e-16f;
        float kv = acc[g] / s;
        size_t o = (size_t)bn*HID + lane + 32*g;
        if (yin){
            kout[o] = yin[o] + dtc*(k1[o] + 2.f*k2[o] + 2.f*k3[o] + kv);
        } else {
            kout[o] = kv;
        }
    }
}

// ---------------- LayerNorm (idx==0 only) ----------------
__global__ void __launch_bounds__(128) k_ln(const float* __restrict__ s, float* __restrict__ d){
    int row = blockIdx.x;
    int t = threadIdx.x;
    __shared__ float sh[4];
    float v = s[(size_t)row*HID + t];

    float a = v;
    #pragma unroll
    for (int o = 16; o > 0; o >>= 1) a += __shfl_xor_sync(0xffffffffu, a, o);
    if ((t & 31) == 0) sh[t >> 5] = a;
    __syncthreads();
    float mean = (sh[0]+sh[1]+sh[2]+sh[3]) * (1.f/HID);

    float dv = v - mean;
    float q = dv*dv;
    __syncthreads();
    #pragma unroll
    for (int o = 16; o > 0; o >>= 1) q += __shfl_xor_sync(0xffffffffu, q, o);
    if ((t & 31) == 0) sh[t >> 5] = q;
    __syncthreads();
    float var = (sh[0]+sh[1]+sh[2]+sh[3]) * (1.f/HID);

    d[(size_t)row*HID + t] = dv / sqrtf(var + 1e-5f);
}

// ---------------- launch ----------------
extern "C" void kernel_launch(void* const* d_in, const int* in_sizes, int n_in,
                              void* d_out, int out_size)
{
    const float* inputs = (const float*)d_in[0];
    const int*   src    = (const int*)  d_in[1];
    const int*   dst    = (const int*)  d_in[2];
    const float* w_in   = (const float*)d_in[3];
    const float* b_in   = (const float*)d_in[4];
    const float* w_gat  = (const float*)d_in[5];
    const float* a_l    = (const float*)d_in[6];
    const float* a_r    = (const float*)d_in[7];
    const float* w_W    = (const float*)d_in[8];
    const float* b_W    = (const float*)d_in[9];
    const float* w_U    = (const float*)d_in[10];
    const float* b_U    = (const float*)d_in[11];
    const float* w_o1   = (const float*)d_in[12];
    const float* b_o1   = (const float*)d_in[13];
    const float* w_o2   = (const float*)d_in[14];
    const float* b_o2   = (const float*)d_in[15];
    float* out = (float*)d_out;

    float *hin, *y, *k1, *k2, *k3, *tmp, *el, *er;
    __half *hp;
    unsigned *wh;
    int *cnt, *cur, *off, *eidx, *srcs;
    cudaGetSymbolAddress((void**)&hin, g_hin);
    cudaGetSymbolAddress((void**)&y,   g_y);
    cudaGetSymbolAddress((void**)&hp,  g_hp);
    cudaGetSymbolAddress((void**)&k1,  g_k1);
    cudaGetSymbolAddress((void**)&k2,  g_k2);
    cudaGetSymbolAddress((void**)&k3,  g_k3);
    cudaGetSymbolAddress((void**)&tmp, g_tmp);
    cudaGetSymbolAddress((void**)&el,  g_el);
    cudaGetSymbolAddress((void**)&er,  g_er);
    cudaGetSymbolAddress((void**)&wh,  g_wh);
    cudaGetSymbolAddress((void**)&cnt, g_cnt);
    cudaGetSymbolAddress((void**)&cur, g_cur);
    cudaGetSymbolAddress((void**)&off, g_off);
    cudaGetSymbolAddress((void**)&eidx,g_eidx);
    cudaGetSymbolAddress((void**)&srcs,g_srcs);

    const float* F0 = (const float*)0;

    static bool attr_set = false;
    if (!attr_set){
        cudaFuncSetAttribute(k_gemm,   cudaFuncAttributeMaxDynamicSharedMemorySize, GEMM_SMEM);
        cudaFuncSetAttribute(k_gemm_h, cudaFuncAttributeMaxDynamicSharedMemorySize, HMMA_SMEM);
        attr_set = true;
    }

    const float dt  = 0.25f;
    const float dtc = dt / 6.0f;

    // prelude
    k_init      <<<B*SEQ*NN, HID>>>(inputs, w_in, b_in, hin, y, cnt, cur);
    k_wsplit    <<<(HID*HID/2+255)/256, 256>>>(w_gat, wh);
    k_csr_count <<<(E+255)/256, 256>>>(dst, cnt);
    k_csr_scan  <<<1, 1024>>>(cnt, off);

    // first RK4 stage-1 GEMM (does not need CSR)
    k_gemm_h<<<125,512,HMMA_SMEM>>>(y, F0, 0.f, wh, hp, el, er, a_l, a_r);

    k_csr_fill  <<<(E+255)/256, 256>>>(dst, off, cur, eidx);
    k_csr_sort  <<<NN, 32>>>(off, eidx);
    k_csr_gather<<<(E+255)/256, 256>>>(eidx, src, srcs);

    for (int idx = 0; idx < SEQ; idx++){
        for (int s = 0; s < 4; s++){
            if (!(idx == 0 && s == 0)){
                k_gemm_h<<<125,512,HMMA_SMEM>>>(y, F0, 0.f, wh, hp, el, er, a_l, a_r);
            }
            k_gat <<<NN,256>>>(hp, el, er, off, srcs, k1, F0,F0,F0,F0, 0.f);
            k_gemm_h<<<125,512,HMMA_SMEM>>>(y, k1, 0.5f*dt, wh, hp, el, er, a_l, a_r);
            k_gat <<<NN,256>>>(hp, el, er, off, srcs, k2, F0,F0,F0,F0, 0.f);
            k_gemm_h<<<125,512,HMMA_SMEM>>>(y, k2, 0.5f*dt, wh, hp, el, er, a_l, a_r);
            k_gat <<<NN,256>>>(hp, el, er, off, srcs, k3, F0,F0,F0,F0, 0.f);
            k_gemm_h<<<125,512,HMMA_SMEM>>>(y, k3, dt, wh, hp, el, er, a_l, a_r);
            k_gat <<<NN,256>>>(hp, el, er, off, srcs, y, y, k1, k2, k3, dtc);
        }
        if (idx > 0){
            // y = LN(tanh(y@w_W + h[idx]@w_U + b_W + b_U)) — LN fused (FFMA path)
            const float* hidx = hin + (size_t)idx * M_ROWS * HID;
            k_gemm<<<125,512,GEMM_SMEM>>>(y, w_W, hidx, w_U, b_W, b_U, y, 1, 1);
        } else {
            k_ln  <<<M_ROWS,128>>>(y, y);
        }
    }

    // out = tanh(y@w_o1 + b_o1) @ w_o2 + b_o2  (FFMA path)
    k_gemm<<<125,512,GEMM_SMEM>>>(y,   w_o1, F0, F0, b_o1, F0, tmp, 1, 0);
    k_gemm<<<125,512,GEMM_SMEM>>>(tmp, w_o2, F0, F0, b_o2, F0, out, 0, 0);
}